// round 1
// baseline (speedup 1.0000x reference)
#include <cuda_runtime.h>
#include <cstdint>

#define NN 50000
#define DD 128
#define HH 128
#define CC 40
#define LL 3
#define GG 4
#define EE 800000
#define XW 512        // D + L*H
#define FW 640        // D*G + D   (basis + silu features per layer)
#define FWO 2560      // XW*G + XW (output-layer features)

// ------------------- device scratch (static: no allocation) -------------------
__device__ int    g_flag;
__device__ int    g_src[EE];
__device__ int    g_dst[EE];
__device__ float  g_dis[NN];
__device__ int    g_cnt[NN];
__device__ int    g_off[NN + 1];
__device__ int    g_fill[NN];
__device__ int    g_csr[EE];
__device__ float  g_xcat[(size_t)NN * XW];
__device__ float  g_F[(size_t)NN * FWO];
__device__ float  g_h1[(size_t)NN * HH];
__device__ float  g_h2[(size_t)NN * HH];
__device__ float  g_Wt[FW * HH];
__device__ float  g_WtO[FWO * 64];
__device__ double g_sum[HH];
__device__ double g_sumsq[HH];
__device__ float  g_bns[HH];
__device__ float  g_bnb[HH];

// ------------------- edge dtype detect + decode -------------------
__global__ void k_detect(const unsigned* e) {
    int z = 0;
    for (int i = 0; i < 16; i++) z += (e[2 * i + 1] == 0u) ? 1 : 0;
    g_flag = (z == 16) ? 1 : 0;   // int64: every high word of first 16 values is 0
}

__global__ void k_decode(const void* ep) {
    int i = blockIdx.x * blockDim.x + threadIdx.x;
    if (i >= EE) return;
    if (g_flag) {
        const long long* e = (const long long*)ep;
        g_src[i] = (int)e[i];
        g_dst[i] = (int)e[EE + i];
    } else {
        const int* e = (const int*)ep;
        g_src[i] = e[i];
        g_dst[i] = e[EE + i];
    }
}

// ------------------- degree / CSR build -------------------
__global__ void k_zero_cnt() {
    int i = blockIdx.x * blockDim.x + threadIdx.x;
    if (i < NN) { g_cnt[i] = 0; g_fill[i] = 0; }
}

__global__ void k_histo() {
    int i = blockIdx.x * blockDim.x + threadIdx.x;
    if (i < EE) atomicAdd(&g_cnt[g_dst[i]], 1);
}

__global__ void k_dis() {
    int i = blockIdx.x * blockDim.x + threadIdx.x;
    if (i < NN) g_dis[i] = rsqrtf((float)(g_cnt[i] + 1));  // +1 self loop
}

__global__ void k_scan() {
    __shared__ int ps[1024];
    int t = threadIdx.x;
    const int CH = (NN + 1023) / 1024;
    int lo = t * CH;
    int hi = lo + CH; if (hi > NN) hi = NN;
    if (lo > NN) lo = NN;
    int s = 0;
    for (int i = lo; i < hi; i++) s += g_cnt[i];
    ps[t] = s;
    __syncthreads();
    for (int d = 1; d < 1024; d <<= 1) {
        int v = (t >= d) ? ps[t - d] : 0;
        __syncthreads();
        ps[t] += v;
        __syncthreads();
    }
    int run = t ? ps[t - 1] : 0;
    for (int i = lo; i < hi; i++) { g_off[i] = run; run += g_cnt[i]; }
    if (t == 1023) g_off[NN] = run;
}

__global__ void k_fill() {
    int i = blockIdx.x * blockDim.x + threadIdx.x;
    if (i >= EE) return;
    int d = g_dst[i];
    int p = g_off[d] + atomicAdd(&g_fill[d], 1);
    g_csr[p] = g_src[i];
}

// ------------------- copy x into xcat[:, 0:128] -------------------
__global__ void k_copyx(const float* __restrict__ x) {
    int i = blockIdx.x * blockDim.x + threadIdx.x;
    if (i >= NN * DD) return;
    g_xcat[(size_t)(i >> 7) * XW + (i & 127)] = x[i];
}

// ------------------- per-layer feature kernel: LN + RBF + SiLU -------------------
__global__ void __launch_bounds__(128) k_feat128(const float* __restrict__ lng,
                                                 const float* __restrict__ lnb,
                                                 int colOff) {
    __shared__ float red[4];
    int n = blockIdx.x, t = threadIdx.x;
    float v = g_xcat[(size_t)n * XW + colOff + t];

    float s = v;
    #pragma unroll
    for (int o = 16; o; o >>= 1) s += __shfl_down_sync(0xffffffffu, s, o);
    if ((t & 31) == 0) red[t >> 5] = s;
    __syncthreads();
    float mean = (red[0] + red[1] + red[2] + red[3]) * (1.0f / 128.0f);
    __syncthreads();

    float dv = v - mean;
    s = dv * dv;
    #pragma unroll
    for (int o = 16; o; o >>= 1) s += __shfl_down_sync(0xffffffffu, s, o);
    if ((t & 31) == 0) red[t >> 5] = s;
    __syncthreads();
    float var = (red[0] + red[1] + red[2] + red[3]) * (1.0f / 128.0f);

    float xn = dv * rsqrtf(var + 1e-5f) * lng[t] + lnb[t];

    const float INV = 0.75f;  // 1/DENOM, DENOM = 4/3
    float z; float4 b;
    z = (xn + 2.0f) * INV;              b.x = __expf(-z * z);
    z = (xn + (2.0f / 3.0f)) * INV;     b.y = __expf(-z * z);
    z = (xn - (2.0f / 3.0f)) * INV;     b.z = __expf(-z * z);
    z = (xn - 2.0f) * INV;              b.w = __expf(-z * z);

    float* Fr = g_F + (size_t)n * FW;
    ((float4*)Fr)[t] = b;                       // basis index d*G+g, d = t
    Fr[512 + t] = v / (1.0f + __expf(-v));      // silu of raw input
}

// ------------------- output feature kernel (width 512) -------------------
__global__ void __launch_bounds__(512) k_feat512(const float* __restrict__ lng,
                                                 const float* __restrict__ lnb) {
    __shared__ float red[16];
    int n = blockIdx.x, t = threadIdx.x;
    float v = g_xcat[(size_t)n * XW + t];

    float s = v;
    #pragma unroll
    for (int o = 16; o; o >>= 1) s += __shfl_down_sync(0xffffffffu, s, o);
    if ((t & 31) == 0) red[t >> 5] = s;
    __syncthreads();
    float tot = 0;
    #pragma unroll
    for (int w = 0; w < 16; w++) tot += red[w];
    float mean = tot * (1.0f / 512.0f);
    __syncthreads();

    float dv = v - mean;
    s = dv * dv;
    #pragma unroll
    for (int o = 16; o; o >>= 1) s += __shfl_down_sync(0xffffffffu, s, o);
    if ((t & 31) == 0) red[t >> 5] = s;
    __syncthreads();
    tot = 0;
    #pragma unroll
    for (int w = 0; w < 16; w++) tot += red[w];
    float var = tot * (1.0f / 512.0f);

    float xn = dv * rsqrtf(var + 1e-5f) * lng[t] + lnb[t];

    const float INV = 0.75f;
    float z; float4 b;
    z = (xn + 2.0f) * INV;              b.x = __expf(-z * z);
    z = (xn + (2.0f / 3.0f)) * INV;     b.y = __expf(-z * z);
    z = (xn - (2.0f / 3.0f)) * INV;     b.z = __expf(-z * z);
    z = (xn - 2.0f) * INV;              b.w = __expf(-z * z);

    float* Fr = g_F + (size_t)n * FWO;
    ((float4*)Fr)[t] = b;
    Fr[2048 + t] = v / (1.0f + __expf(-v));
}

// ------------------- weight transposes -------------------
__global__ void k_transW(const float* __restrict__ sw, const float* __restrict__ bw) {
    int i = blockIdx.x * blockDim.x + threadIdx.x;
    if (i >= FW * HH) return;
    int k = i / HH, j = i % HH;
    g_Wt[i] = (k < 512) ? sw[j * 512 + k] : bw[j * 128 + (k - 512)];
}

__global__ void k_transWO(const float* __restrict__ swo, const float* __restrict__ bwo) {
    int i = blockIdx.x * blockDim.x + threadIdx.x;
    if (i >= FWO * 64) return;
    int k = i / 64, j = i % 64;
    float v = 0.0f;
    if (j < CC) v = (k < 2048) ? swo[j * 2048 + k] : bwo[j * 512 + (k - 2048)];
    g_WtO[i] = v;
}

// ------------------- layer GEMM: h1[N,128] = F[N,640] @ Wt + bb -------------------
__global__ void __launch_bounds__(256) k_gemm_layer(const float* __restrict__ bb) {
    __shared__ float As[16][128];
    __shared__ float Bs[16][128];
    int bm = blockIdx.x * 128;
    int tid = threadIdx.x;
    int tr = tid >> 4, tc = tid & 15;
    float acc[8][8];
    #pragma unroll
    for (int i = 0; i < 8; i++)
        #pragma unroll
        for (int j = 0; j < 8; j++) acc[i][j] = 0.0f;

    for (int k0 = 0; k0 < FW; k0 += 16) {
        #pragma unroll
        for (int l = 0; l < 2; l++) {
            int idx = tid + l * 256;          // 0..511 float4 slots
            int m = idx >> 2;                 // 0..127
            int k4 = (idx & 3) * 4;
            int row = bm + m;
            float4 a = make_float4(0.f, 0.f, 0.f, 0.f);
            if (row < NN) a = *(const float4*)(g_F + (size_t)row * FW + k0 + k4);
            As[k4 + 0][m] = a.x; As[k4 + 1][m] = a.y;
            As[k4 + 2][m] = a.z; As[k4 + 3][m] = a.w;
        }
        #pragma unroll
        for (int l = 0; l < 2; l++) {
            int idx = tid + l * 256;
            int k = idx >> 5;                 // 0..15
            int n4 = (idx & 31) * 4;
            *(float4*)&Bs[k][n4] = *(const float4*)(g_Wt + (k0 + k) * HH + n4);
        }
        __syncthreads();
        #pragma unroll
        for (int kk = 0; kk < 16; kk++) {
            float ra[8], rb[8];
            #pragma unroll
            for (int i = 0; i < 8; i++) ra[i] = As[kk][tr * 8 + i];
            #pragma unroll
            for (int j = 0; j < 8; j++) rb[j] = Bs[kk][tc * 8 + j];
            #pragma unroll
            for (int i = 0; i < 8; i++)
                #pragma unroll
                for (int j = 0; j < 8; j++) acc[i][j] += ra[i] * rb[j];
        }
        __syncthreads();
    }
    #pragma unroll
    for (int i = 0; i < 8; i++) {
        int row = bm + tr * 8 + i;
        if (row < NN) {
            float* C = g_h1 + (size_t)row * HH + tc * 8;
            #pragma unroll
            for (int j = 0; j < 8; j++) C[j] = acc[i][j] + bb[tc * 8 + j];
        }
    }
}

// ------------------- output GEMM: out[N,40] = F[N,2560] @ WtO + bb -------------------
__global__ void __launch_bounds__(256) k_gemm_out(const float* __restrict__ bbo,
                                                  float* __restrict__ out) {
    __shared__ float As[16][64];
    __shared__ float Bs[16][64];
    int bm = blockIdx.x * 64;
    int tid = threadIdx.x;
    int tr = tid >> 4, tc = tid & 15;
    float acc[4][4];
    #pragma unroll
    for (int i = 0; i < 4; i++)
        #pragma unroll
        for (int j = 0; j < 4; j++) acc[i][j] = 0.0f;

    for (int k0 = 0; k0 < FWO; k0 += 16) {
        {
            int m = tid >> 2;                 // 0..63
            int k4 = (tid & 3) * 4;
            int row = bm + m;
            float4 a = make_float4(0.f, 0.f, 0.f, 0.f);
            if (row < NN) a = *(const float4*)(g_F + (size_t)row * FWO + k0 + k4);
            As[k4 + 0][m] = a.x; As[k4 + 1][m] = a.y;
            As[k4 + 2][m] = a.z; As[k4 + 3][m] = a.w;
        }
        {
            int k = tid >> 4;                 // 0..15
            int n4 = (tid & 15) * 4;
            *(float4*)&Bs[k][n4] = *(const float4*)(g_WtO + (k0 + k) * 64 + n4);
        }
        __syncthreads();
        #pragma unroll
        for (int kk = 0; kk < 16; kk++) {
            float ra[4], rb[4];
            #pragma unroll
            for (int i = 0; i < 4; i++) ra[i] = As[kk][tr * 4 + i];
            #pragma unroll
            for (int j = 0; j < 4; j++) rb[j] = Bs[kk][tc * 4 + j];
            #pragma unroll
            for (int i = 0; i < 4; i++)
                #pragma unroll
                for (int j = 0; j < 4; j++) acc[i][j] += ra[i] * rb[j];
        }
        __syncthreads();
    }
    #pragma unroll
    for (int i = 0; i < 4; i++) {
        int row = bm + tr * 4 + i;
        if (row >= NN) continue;
        #pragma unroll
        for (int j = 0; j < 4; j++) {
            int col = tc * 4 + j;
            if (col < CC) out[(size_t)row * CC + col] = acc[i][j] + bbo[col];
        }
    }
}

// ------------------- GCN aggregation (pull via CSR, no atomics) -------------------
__global__ void __launch_bounds__(256) k_gcn() {
    int warp = blockIdx.x * 8 + (threadIdx.x >> 5);
    if (warp >= NN) return;
    int l = threadIdx.x & 31;
    float dn = g_dis[warp];
    float4 acc = make_float4(0.f, 0.f, 0.f, 0.f);
    int lo = g_off[warp], hi = g_off[warp + 1];
    for (int e = lo; e < hi; e++) {
        int sidx = g_csr[e];
        float w = g_dis[sidx];
        float4 hv = *(const float4*)(g_h1 + (size_t)sidx * HH + l * 4);
        acc.x += w * hv.x; acc.y += w * hv.y;
        acc.z += w * hv.z; acc.w += w * hv.w;
    }
    float4 self = *(const float4*)(g_h1 + (size_t)warp * HH + l * 4);
    float dn2 = dn * dn;
    float4 r;
    r.x = dn * acc.x + dn2 * self.x;
    r.y = dn * acc.y + dn2 * self.y;
    r.z = dn * acc.z + dn2 * self.z;
    r.w = dn * acc.w + dn2 * self.w;
    *(float4*)(g_h2 + (size_t)warp * HH + l * 4) = r;
}

// ------------------- BatchNorm -------------------
__global__ void k_zero_stats() {
    int t = threadIdx.x;
    g_sum[t] = 0.0; g_sumsq[t] = 0.0;
}

__global__ void __launch_bounds__(128) k_bn_partial() {
    int t = threadIdx.x;
    int r0 = blockIdx.x * 64;
    float s = 0.f, s2 = 0.f;
    #pragma unroll 4
    for (int r = 0; r < 64; r++) {
        int row = r0 + r;
        if (row < NN) {
            float v = g_h2[(size_t)row * HH + t];
            s += v; s2 += v * v;
        }
    }
    atomicAdd(&g_sum[t], (double)s);
    atomicAdd(&g_sumsq[t], (double)s2);
}

__global__ void k_bn_finalize(const float* __restrict__ bng, const float* __restrict__ bnb) {
    int t = threadIdx.x;
    double m = g_sum[t] / (double)NN;
    double var = g_sumsq[t] / (double)NN - m * m;
    float sc = bng[t] * rsqrtf((float)var + 1e-5f);
    g_bns[t] = sc;
    g_bnb[t] = bnb[t] - (float)m * sc;
}

__global__ void k_bn_apply(int layer) {
    int i = blockIdx.x * blockDim.x + threadIdx.x;
    if (i >= NN * HH) return;
    int c = i & 127;
    int n = i >> 7;
    g_xcat[(size_t)n * XW + DD + layer * HH + c] = g_h2[i] * g_bns[c] + g_bnb[c];
}

// ------------------- launch -------------------
extern "C" void kernel_launch(void* const* d_in, const int* in_sizes, int n_in,
                              void* d_out, int out_size) {
    const float* x      = (const float*)d_in[0];
    const void*  eidx   = d_in[1];
    const float* ln_g   = (const float*)d_in[2];
    const float* ln_b   = (const float*)d_in[3];
    const float* sw     = (const float*)d_in[4];
    const float* bw     = (const float*)d_in[5];
    const float* bb     = (const float*)d_in[6];
    // d_in[7] = gcn_bias: provably cancelled by BatchNorm (per-column shift) -> skipped
    const float* bn_g   = (const float*)d_in[8];
    const float* bn_b   = (const float*)d_in[9];
    const float* ln_go  = (const float*)d_in[10];
    const float* ln_bo  = (const float*)d_in[11];
    const float* sw_o   = (const float*)d_in[12];
    const float* bw_o   = (const float*)d_in[13];
    const float* bb_o   = (const float*)d_in[14];
    float* out = (float*)d_out;

    // graph / CSR build
    k_detect<<<1, 1>>>((const unsigned*)eidx);
    k_decode<<<(EE + 255) / 256, 256>>>(eidx);
    k_zero_cnt<<<(NN + 255) / 256, 256>>>();
    k_histo<<<(EE + 255) / 256, 256>>>();
    k_dis<<<(NN + 255) / 256, 256>>>();
    k_scan<<<1, 1024>>>();
    k_fill<<<(EE + 255) / 256, 256>>>();

    k_copyx<<<(NN * DD + 255) / 256, 256>>>(x);

    for (int i = 0; i < LL; i++) {
        k_feat128<<<NN, 128>>>(ln_g + i * DD, ln_b + i * DD, i * 128);
        k_transW<<<(FW * HH + 255) / 256, 256>>>(sw + (size_t)i * HH * 512,
                                                 bw + (size_t)i * HH * DD);
        k_gemm_layer<<<(NN + 127) / 128, 256>>>(bb + i * HH);
        k_gcn<<<(NN + 7) / 8, 256>>>();
        k_zero_stats<<<1, 128>>>();
        k_bn_partial<<<(NN + 63) / 64, 128>>>();
        k_bn_finalize<<<1, 128>>>(bn_g + i * HH, bn_b + i * HH);
        k_bn_apply<<<(NN * HH + 255) / 256, 256>>>(i);
    }

    k_feat512<<<NN, 512>>>(ln_go, ln_bo);
    k_transWO<<<(FWO * 64 + 255) / 256, 256>>>(sw_o, bw_o);
    k_gemm_out<<<(NN + 63) / 64, 256>>>(bb_o, out);
}

// round 3
// speedup vs baseline: 1.2262x; 1.2262x over previous
#include <cuda_runtime.h>
#include <cstdint>

#define NN 50000
#define DD 128
#define HH 128
#define CC 40
#define LL 3
#define EE 800000
#define XW 512        // D + L*H
#define FW 640        // D*G + D
#define FWO 2560      // XW*G + XW

typedef unsigned long long ull;

// ------------------- device scratch (static: no allocation) -------------------
__device__ int    g_flag;
__device__ int    g_src[EE];
__device__ int    g_dst[EE];
__device__ float  g_dis[NN];
__device__ int    g_cnt[NN];
__device__ int    g_off[NN + 1];
__device__ int    g_fill[NN];
__device__ int    g_csr[EE];
__device__ float  g_xcat[(size_t)NN * XW];
__device__ float  g_XNT[(size_t)512 * NN];   // transposed layernormed values [d][N]
__device__ float  g_ST [(size_t)512 * NN];   // transposed silu values       [d][N]
__device__ float  g_h1[(size_t)NN * HH];
__device__ float  g_h2[(size_t)NN * HH];
__device__ float  g_Wt[FW * HH];
__device__ float  g_WtO[FWO * 64];
__device__ double g_sum[HH];
__device__ double g_sumsq[HH];
__device__ float  g_bns[HH];
__device__ float  g_bnb[HH];

// ------------------- f32x2 packed math helpers -------------------
__device__ __forceinline__ ull pk2(float x, float y) {
    ull r; asm("mov.b64 %0, {%1, %2};" : "=l"(r) : "f"(x), "f"(y)); return r;
}
__device__ __forceinline__ void fma2(ull& d, ull a, ull b) {
    asm("fma.rn.f32x2 %0, %1, %2, %0;" : "+l"(d) : "l"(a), "l"(b));
}
__device__ __forceinline__ float2 upk(ull v) {
    float2 f; asm("mov.b64 {%0, %1}, %2;" : "=f"(f.x), "=f"(f.y) : "l"(v)); return f;
}

// ------------------- edge dtype detect + decode -------------------
__global__ void k_detect(const unsigned* e) {
    int z = 0;
    for (int i = 0; i < 16; i++) z += (e[2 * i + 1] == 0u) ? 1 : 0;
    g_flag = (z == 16) ? 1 : 0;
}

__global__ void k_decode(const void* ep) {
    int i = blockIdx.x * blockDim.x + threadIdx.x;
    if (i >= EE) return;
    if (g_flag) {
        const long long* e = (const long long*)ep;
        g_src[i] = (int)e[i];
        g_dst[i] = (int)e[EE + i];
    } else {
        const int* e = (const int*)ep;
        g_src[i] = e[i];
        g_dst[i] = e[EE + i];
    }
}

// ------------------- degree / CSR build -------------------
__global__ void k_zero_cnt() {
    int i = blockIdx.x * blockDim.x + threadIdx.x;
    if (i < NN) { g_cnt[i] = 0; g_fill[i] = 0; }
}
__global__ void k_histo() {
    int i = blockIdx.x * blockDim.x + threadIdx.x;
    if (i < EE) atomicAdd(&g_cnt[g_dst[i]], 1);
}
__global__ void k_dis() {
    int i = blockIdx.x * blockDim.x + threadIdx.x;
    if (i < NN) g_dis[i] = rsqrtf((float)(g_cnt[i] + 1));
}
__global__ void k_scan() {
    __shared__ int ps[1024];
    int t = threadIdx.x;
    const int CH = (NN + 1023) / 1024;
    int lo = t * CH;
    int hi = lo + CH; if (hi > NN) hi = NN;
    if (lo > NN) lo = NN;
    int s = 0;
    for (int i = lo; i < hi; i++) s += g_cnt[i];
    ps[t] = s;
    __syncthreads();
    for (int d = 1; d < 1024; d <<= 1) {
        int v = (t >= d) ? ps[t - d] : 0;
        __syncthreads();
        ps[t] += v;
        __syncthreads();
    }
    int run = t ? ps[t - 1] : 0;
    for (int i = lo; i < hi; i++) { g_off[i] = run; run += g_cnt[i]; }
    if (t == 1023) g_off[NN] = run;
}
__global__ void k_fill() {
    int i = blockIdx.x * blockDim.x + threadIdx.x;
    if (i >= EE) return;
    int d = g_dst[i];
    int p = g_off[d] + atomicAdd(&g_fill[d], 1);
    g_csr[p] = g_src[i];
}

// ------------------- copy x into xcat[:, 0:128] -------------------
__global__ void k_copyx(const float* __restrict__ x) {
    int i = blockIdx.x * blockDim.x + threadIdx.x;
    if (i >= NN * DD) return;
    g_xcat[(size_t)(i >> 7) * XW + (i & 127)] = x[i];
}

// ------------------- prep: LayerNorm + SiLU, transposed outputs -------------------
// W = feature width, RPB = rows per block (256 threads, 8 warps)
template<int W, int RPB>
__global__ void __launch_bounds__(256) k_prep(int colOff,
                                              const float* __restrict__ lng,
                                              const float* __restrict__ lnb) {
    __shared__ float xs[RPB][W + 1];
    __shared__ float ss[RPB][W + 1];
    int warp = threadIdx.x >> 5, lane = threadIdx.x & 31;
    const int RPW = RPB / 8;
    #pragma unroll
    for (int rr = 0; rr < RPW; rr++) {
        int r = warp * RPW + rr;
        int gr = blockIdx.x * RPB + r;
        if (gr < NN) {
            float v[W / 32];
            float s = 0.f;
            #pragma unroll
            for (int j = 0; j < W / 32; j++) {
                v[j] = g_xcat[(size_t)gr * XW + colOff + lane + j * 32];
                s += v[j];
            }
            #pragma unroll
            for (int o = 16; o; o >>= 1) s += __shfl_xor_sync(0xffffffffu, s, o);
            float mean = s * (1.0f / W);
            float q = 0.f;
            #pragma unroll
            for (int j = 0; j < W / 32; j++) { float d = v[j] - mean; q += d * d; }
            #pragma unroll
            for (int o = 16; o; o >>= 1) q += __shfl_xor_sync(0xffffffffu, q, o);
            float rstd = rsqrtf(q * (1.0f / W) + 1e-5f);
            #pragma unroll
            for (int j = 0; j < W / 32; j++) {
                int c = lane + j * 32;
                xs[r][c] = (v[j] - mean) * rstd * lng[c] + lnb[c];
                ss[r][c] = v[j] / (1.0f + __expf(-v[j]));
            }
        }
    }
    __syncthreads();
    const int LG = (RPB == 32) ? 5 : 3;
    int base = blockIdx.x * RPB;
    #pragma unroll 4
    for (int idx = threadIdx.x; idx < RPB * W; idx += 256) {
        int r = idx & (RPB - 1);
        int d = idx >> LG;
        int gr = base + r;
        if (gr < NN) {
            g_XNT[(size_t)d * NN + gr] = xs[r][d];
            g_ST [(size_t)d * NN + gr] = ss[r][d];
        }
    }
}

// ------------------- weight transposes -------------------
__global__ void k_transW(const float* __restrict__ sw, const float* __restrict__ bw) {
    int i = blockIdx.x * blockDim.x + threadIdx.x;
    if (i >= FW * HH) return;
    int k = i / HH, j = i % HH;
    g_Wt[i] = (k < 512) ? sw[j * 512 + k] : bw[j * 128 + (k - 512)];
}
__global__ void k_transWO(const float* __restrict__ swo, const float* __restrict__ bwo) {
    int i = blockIdx.x * blockDim.x + threadIdx.x;
    if (i >= FWO * 64) return;
    int k = i / 64, j = i % 64;
    float v = 0.0f;
    if (j < CC) v = (k < 2048) ? swo[j * 2048 + k] : bwo[j * 512 + (k - 2048)];
    g_WtO[i] = v;
}

// ------------------- fused layer GEMM: h1[N,128] = Basis(XN)|SiLU @ Wt + bb -------------------
__global__ void __launch_bounds__(256) k_gemm_layer(const float* __restrict__ bb) {
    __shared__ float As[32][128];
    __shared__ float Bs[32][128];
    int bm = blockIdx.x * 128;
    int tid = threadIdx.x;
    int tr = tid >> 4, tc = tid & 15;
    ull acc[8][4];
    #pragma unroll
    for (int i = 0; i < 8; i++)
        #pragma unroll
        for (int j = 0; j < 4; j++) acc[i][j] = 0ull;

    for (int k0 = 0; k0 < FW; k0 += 32) {
        if (k0 < 512) {
            // basis region: generate exp on the fly from transposed XN
            int d0 = k0 >> 2;
            #pragma unroll
            for (int it = 0; it < 4; it++) {
                int p = tid + it * 256;
                int row = p & 127, di = p >> 7;
                int gr = bm + row;
                float xn = (gr < NN) ? g_XNT[(size_t)(d0 + di) * NN + gr] : 0.f;
                float z0 = (xn + 2.0f) * 0.75f;
                float z1 = (xn + 0.66666667f) * 0.75f;
                float z2 = (xn - 0.66666667f) * 0.75f;
                float z3 = (xn - 2.0f) * 0.75f;
                As[di * 4 + 0][row] = __expf(-z0 * z0);
                As[di * 4 + 1][row] = __expf(-z1 * z1);
                As[di * 4 + 2][row] = __expf(-z2 * z2);
                As[di * 4 + 3][row] = __expf(-z3 * z3);
            }
        } else {
            // silu region
            #pragma unroll
            for (int it = 0; it < 16; it++) {
                int p = tid + it * 256;
                int row = p & 127, k = p >> 7;
                int gr = bm + row;
                As[k][row] = (gr < NN) ? g_ST[(size_t)(k0 - 512 + k) * NN + gr] : 0.f;
            }
        }
        #pragma unroll
        for (int it = 0; it < 4; it++) {
            int p = tid + it * 256;
            int k = p >> 5, n4 = (p & 31) * 4;
            *(float4*)&Bs[k][n4] = *(const float4*)&g_Wt[(k0 + k) * HH + n4];
        }
        __syncthreads();
        #pragma unroll
        for (int kk = 0; kk < 32; kk++) {
            float4 a0 = *(float4*)&As[kk][tr * 8];
            float4 a1 = *(float4*)&As[kk][tr * 8 + 4];
            const ull* bp = (const ull*)&Bs[kk][tc * 8];
            ull rb0 = bp[0], rb1 = bp[1], rb2 = bp[2], rb3 = bp[3];
            float ra[8] = {a0.x, a0.y, a0.z, a0.w, a1.x, a1.y, a1.z, a1.w};
            #pragma unroll
            for (int i = 0; i < 8; i++) {
                ull ra2 = pk2(ra[i], ra[i]);
                fma2(acc[i][0], ra2, rb0);
                fma2(acc[i][1], ra2, rb1);
                fma2(acc[i][2], ra2, rb2);
                fma2(acc[i][3], ra2, rb3);
            }
        }
        __syncthreads();
    }
    #pragma unroll
    for (int i = 0; i < 8; i++) {
        int row = bm + tr * 8 + i;
        if (row < NN) {
            float* C = g_h1 + (size_t)row * HH + tc * 8;
            #pragma unroll
            for (int j = 0; j < 4; j++) {
                float2 f = upk(acc[i][j]);
                C[2 * j + 0] = f.x + bb[tc * 8 + 2 * j + 0];
                C[2 * j + 1] = f.y + bb[tc * 8 + 2 * j + 1];
            }
        }
    }
}

// ------------------- fused output GEMM: out[N,40] = Basis(XN)|SiLU @ WtO + bb -------------------
__global__ void __launch_bounds__(256) k_gemm_out(const float* __restrict__ bbo,
                                                  float* __restrict__ out) {
    __shared__ float As[32][256];
    __shared__ float Bs[32][64];
    int bm = blockIdx.x * 256;
    int tid = threadIdx.x;
    int tr = tid >> 3, tc = tid & 7;   // 32 x 8 threads; 8 rows x 6 cols each
    ull acc[8][3];
    #pragma unroll
    for (int i = 0; i < 8; i++)
        #pragma unroll
        for (int j = 0; j < 3; j++) acc[i][j] = 0ull;

    bool full = (bm + 256 <= NN);
    for (int k0 = 0; k0 < FWO; k0 += 32) {
        if (k0 < 2048) {
            int d0 = k0 >> 2;
            #pragma unroll
            for (int it = 0; it < 8; it++) {
                int p = tid + it * 256;
                int row = p & 255, di = p >> 8;
                int gr = bm + row;
                float xn = (gr < NN) ? g_XNT[(size_t)(d0 + di) * NN + gr] : 0.f;
                float z0 = (xn + 2.0f) * 0.75f;
                float z1 = (xn + 0.66666667f) * 0.75f;
                float z2 = (xn - 0.66666667f) * 0.75f;
                float z3 = (xn - 2.0f) * 0.75f;
                As[di * 4 + 0][row] = __expf(-z0 * z0);
                As[di * 4 + 1][row] = __expf(-z1 * z1);
                As[di * 4 + 2][row] = __expf(-z2 * z2);
                As[di * 4 + 3][row] = __expf(-z3 * z3);
            }
        } else {
            if (full) {
                #pragma unroll
                for (int it = 0; it < 8; it++) {
                    int p = tid + it * 256;       // 2048 float4 slots
                    int k = p >> 6, m4 = (p & 63) * 4;
                    *(float4*)&As[k][m4] =
                        *(const float4*)&g_ST[(size_t)(k0 - 2048 + k) * NN + bm + m4];
                }
            } else {
                #pragma unroll
                for (int it = 0; it < 32; it++) {
                    int p = tid + it * 256;       // 8192 scalars
                    int row = p & 255, k = p >> 8;
                    int gr = bm + row;
                    As[k][row] = (gr < NN) ? g_ST[(size_t)(k0 - 2048 + k) * NN + gr] : 0.f;
                }
            }
        }
        #pragma unroll
        for (int it = 0; it < 2; it++) {
            int p = tid + it * 256;
            int k = p >> 4, n4 = (p & 15) * 4;
            *(float4*)&Bs[k][n4] = *(const float4*)&g_WtO[(k0 + k) * 64 + n4];
        }
        __syncthreads();
        #pragma unroll
        for (int kk = 0; kk < 32; kk++) {
            float4 a0 = *(float4*)&As[kk][tr * 8];
            float4 a1 = *(float4*)&As[kk][tr * 8 + 4];
            const ull* bp = (const ull*)&Bs[kk][tc * 6];
            ull rb0 = bp[0], rb1 = bp[1], rb2 = bp[2];
            float ra[8] = {a0.x, a0.y, a0.z, a0.w, a1.x, a1.y, a1.z, a1.w};
            #pragma unroll
            for (int i = 0; i < 8; i++) {
                ull ra2 = pk2(ra[i], ra[i]);
                fma2(acc[i][0], ra2, rb0);
                fma2(acc[i][1], ra2, rb1);
                fma2(acc[i][2], ra2, rb2);
            }
        }
        __syncthreads();
    }
    #pragma unroll
    for (int i = 0; i < 8; i++) {
        int row = bm + tr * 8 + i;
        if (row >= NN) continue;
        #pragma unroll
        for (int j = 0; j < 3; j++) {
            float2 f = upk(acc[i][j]);
            int c = tc * 6 + 2 * j;
            if (c < CC)     out[(size_t)row * CC + c]     = f.x + bbo[c];
            if (c + 1 < CC) out[(size_t)row * CC + c + 1] = f.y + bbo[c + 1];
        }
    }
}

// ------------------- GCN aggregation (pull via CSR, no atomics) -------------------
__global__ void __launch_bounds__(256) k_gcn() {
    int warp = blockIdx.x * 8 + (threadIdx.x >> 5);
    if (warp >= NN) return;
    int l = threadIdx.x & 31;
    float dn = g_dis[warp];
    float4 acc = make_float4(0.f, 0.f, 0.f, 0.f);
    int lo = g_off[warp], hi = g_off[warp + 1];
    for (int e = lo; e < hi; e++) {
        int sidx = g_csr[e];
        float w = g_dis[sidx];
        float4 hv = *(const float4*)(g_h1 + (size_t)sidx * HH + l * 4);
        acc.x += w * hv.x; acc.y += w * hv.y;
        acc.z += w * hv.z; acc.w += w * hv.w;
    }
    float4 self = *(const float4*)(g_h1 + (size_t)warp * HH + l * 4);
    float dn2 = dn * dn;
    float4 r;
    r.x = dn * acc.x + dn2 * self.x;
    r.y = dn * acc.y + dn2 * self.y;
    r.z = dn * acc.z + dn2 * self.z;
    r.w = dn * acc.w + dn2 * self.w;
    *(float4*)(g_h2 + (size_t)warp * HH + l * 4) = r;
}

// ------------------- BatchNorm -------------------
__global__ void k_zero_stats() {
    int t = threadIdx.x;
    g_sum[t] = 0.0; g_sumsq[t] = 0.0;
}
__global__ void __launch_bounds__(128) k_bn_partial() {
    int t = threadIdx.x;
    int r0 = blockIdx.x * 64;
    float s = 0.f, s2 = 0.f;
    #pragma unroll 4
    for (int r = 0; r < 64; r++) {
        int row = r0 + r;
        if (row < NN) {
            float v = g_h2[(size_t)row * HH + t];
            s += v; s2 += v * v;
        }
    }
    atomicAdd(&g_sum[t], (double)s);
    atomicAdd(&g_sumsq[t], (double)s2);
}
__global__ void k_bn_finalize(const float* __restrict__ bng, const float* __restrict__ bnb) {
    int t = threadIdx.x;
    double m = g_sum[t] / (double)NN;
    double var = g_sumsq[t] / (double)NN - m * m;
    float sc = bng[t] * rsqrtf((float)var + 1e-5f);
    g_bns[t] = sc;
    g_bnb[t] = bnb[t] - (float)m * sc;
}
__global__ void k_bn_apply(int layer) {
    int i = blockIdx.x * blockDim.x + threadIdx.x;
    if (i >= NN * HH) return;
    int c = i & 127;
    int n = i >> 7;
    g_xcat[(size_t)n * XW + DD + layer * HH + c] = g_h2[i] * g_bns[c] + g_bnb[c];
}

// ------------------- launch -------------------
extern "C" void kernel_launch(void* const* d_in, const int* in_sizes, int n_in,
                              void* d_out, int out_size) {
    const float* x      = (const float*)d_in[0];
    const void*  eidx   = d_in[1];
    const float* ln_g   = (const float*)d_in[2];
    const float* ln_b   = (const float*)d_in[3];
    const float* sw     = (const float*)d_in[4];
    const float* bw     = (const float*)d_in[5];
    const float* bb     = (const float*)d_in[6];
    // d_in[7] = gcn_bias: cancelled exactly by the following BatchNorm -> skipped
    const float* bn_g   = (const float*)d_in[8];
    const float* bn_b   = (const float*)d_in[9];
    const float* ln_go  = (const float*)d_in[10];
    const float* ln_bo  = (const float*)d_in[11];
    const float* sw_o   = (const float*)d_in[12];
    const float* bw_o   = (const float*)d_in[13];
    const float* bb_o   = (const float*)d_in[14];
    float* out = (float*)d_out;

    // graph / CSR build
    k_detect<<<1, 1>>>((const unsigned*)eidx);
    k_decode<<<(EE + 255) / 256, 256>>>(eidx);
    k_zero_cnt<<<(NN + 255) / 256, 256>>>();
    k_histo<<<(EE + 255) / 256, 256>>>();
    k_dis<<<(NN + 255) / 256, 256>>>();
    k_scan<<<1, 1024>>>();
    k_fill<<<(EE + 255) / 256, 256>>>();

    k_copyx<<<(NN * DD + 255) / 256, 256>>>(x);

    for (int i = 0; i < LL; i++) {
        k_prep<128, 32><<<(NN + 31) / 32, 256>>>(i * 128, ln_g + i * DD, ln_b + i * DD);
        k_transW<<<(FW * HH + 255) / 256, 256>>>(sw + (size_t)i * HH * 512,
                                                 bw + (size_t)i * HH * DD);
        k_gemm_layer<<<(NN + 127) / 128, 256>>>(bb + i * HH);
        k_gcn<<<(NN + 7) / 8, 256>>>();
        k_zero_stats<<<1, 128>>>();
        k_bn_partial<<<(NN + 63) / 64, 128>>>();
        k_bn_finalize<<<1, 128>>>(bn_g + i * HH, bn_b + i * HH);
        k_bn_apply<<<(NN * HH + 255) / 256, 256>>>(i);
    }

    k_prep<512, 8><<<(NN + 7) / 8, 256>>>(0, ln_go, ln_bo);
    k_transWO<<<(FWO * 64 + 255) / 256, 256>>>(sw_o, bw_o);
    k_gemm_out<<<(NN + 255) / 256, 256>>>(bb_o, out);
}

// round 5
// speedup vs baseline: 1.8765x; 1.5304x over previous
#include <cuda_runtime.h>
#include <cstdint>

#define NN 50000
#define DD 128
#define HH 128
#define CC 40
#define LL 3
#define EE 800000
#define XW 512        // D + L*H
#define LSTR 40       // padded SMEM row stride in bf16 units (80 bytes)

typedef unsigned long long ull;

// ------------------- device scratch (static: no allocation) -------------------
__device__ int    g_flag;
__device__ int    g_src[EE];
__device__ int    g_dst[EE];
__device__ float  g_dis[NN];
__device__ int    g_cnt[NN];
__device__ int    g_off[NN + 1];
__device__ int    g_fill[NN];
__device__ int    g_csr[EE];
__device__ float  g_xcat[(size_t)NN * XW];
__device__ float  g_XNT[(size_t)512 * NN + 256];  // transposed layernormed values [d][N] (+pad)
__device__ float  g_ST [(size_t)512 * NN + 256];  // transposed silu values       [d][N] (+pad)
__device__ float  g_h1[(size_t)NN * HH];
__device__ float  g_h2[(size_t)NN * HH];
__device__ unsigned short g_WBh[20 * 128 * 32];   // layer B bf16-hi  [chunk][n][k]
__device__ unsigned short g_WBl[20 * 128 * 32];   // layer B bf16-lo
__device__ unsigned short g_WOh[80 * 64 * 32];    // output B bf16-hi [chunk][n][k]
__device__ unsigned short g_WOl[80 * 64 * 32];
__device__ double g_sum[HH];
__device__ double g_sumsq[HH];
__device__ float  g_bns[HH];
__device__ float  g_bnb[HH];

// ------------------- helpers -------------------
__device__ __forceinline__ uint32_t smem_u32(const void* p) {
    uint32_t a;
    asm("{ .reg .u64 t; cvta.to.shared.u64 t, %1; cvt.u32.u64 %0, t; }" : "=r"(a) : "l"(p));
    return a;
}
__device__ __forceinline__ uint32_t pkbf(float a, float b) {   // [bf16(a) lo16 | bf16(b) hi16]
    uint32_t r;
    asm("cvt.rn.bf16x2.f32 %0, %1, %2;" : "=r"(r) : "f"(b), "f"(a));
    return r;
}
__device__ __forceinline__ float lo2f(uint32_t v) { return __uint_as_float(v << 16); }
__device__ __forceinline__ float hi2f(uint32_t v) { return __uint_as_float(v & 0xffff0000u); }

__device__ __forceinline__ void ldsm4(uint32_t& r0, uint32_t& r1, uint32_t& r2, uint32_t& r3,
                                      uint32_t a) {
    asm volatile("ldmatrix.sync.aligned.m8n8.x4.shared.b16 {%0,%1,%2,%3}, [%4];"
                 : "=r"(r0), "=r"(r1), "=r"(r2), "=r"(r3) : "r"(a));
}
__device__ __forceinline__ void mmabf(float* c, const uint32_t* a, uint32_t b0, uint32_t b1) {
    asm volatile("mma.sync.aligned.m16n8k16.row.col.f32.bf16.bf16.f32 "
                 "{%0,%1,%2,%3}, {%4,%5,%6,%7}, {%8,%9}, {%0,%1,%2,%3};"
                 : "+f"(c[0]), "+f"(c[1]), "+f"(c[2]), "+f"(c[3])
                 : "r"(a[0]), "r"(a[1]), "r"(a[2]), "r"(a[3]), "r"(b0), "r"(b1));
}

// ------------------- edge dtype detect + decode -------------------
__global__ void k_detect(const unsigned* e) {
    int z = 0;
    for (int i = 0; i < 16; i++) z += (e[2 * i + 1] == 0u) ? 1 : 0;
    g_flag = (z == 16) ? 1 : 0;
}
__global__ void k_decode(const void* ep) {
    int i = blockIdx.x * blockDim.x + threadIdx.x;
    if (i >= EE) return;
    if (g_flag) {
        const long long* e = (const long long*)ep;
        g_src[i] = (int)e[i];
        g_dst[i] = (int)e[EE + i];
    } else {
        const int* e = (const int*)ep;
        g_src[i] = e[i];
        g_dst[i] = e[EE + i];
    }
}

// ------------------- degree / CSR build -------------------
__global__ void k_zero_cnt() {
    int i = blockIdx.x * blockDim.x + threadIdx.x;
    if (i < NN) { g_cnt[i] = 0; g_fill[i] = 0; }
}
__global__ void k_histo() {
    int i = blockIdx.x * blockDim.x + threadIdx.x;
    if (i < EE) atomicAdd(&g_cnt[g_dst[i]], 1);
}
__global__ void k_dis() {
    int i = blockIdx.x * blockDim.x + threadIdx.x;
    if (i < NN) g_dis[i] = rsqrtf((float)(g_cnt[i] + 1));
}
__global__ void k_scan() {
    __shared__ int ps[1024];
    int t = threadIdx.x;
    const int CH = (NN + 1023) / 1024;
    int lo = t * CH;
    int hi = lo + CH; if (hi > NN) hi = NN;
    if (lo > NN) lo = NN;
    int s = 0;
    for (int i = lo; i < hi; i++) s += g_cnt[i];
    ps[t] = s;
    __syncthreads();
    for (int d = 1; d < 1024; d <<= 1) {
        int v = (t >= d) ? ps[t - d] : 0;
        __syncthreads();
        ps[t] += v;
        __syncthreads();
    }
    int run = t ? ps[t - 1] : 0;
    for (int i = lo; i < hi; i++) { g_off[i] = run; run += g_cnt[i]; }
    if (t == 1023) g_off[NN] = run;
}
__global__ void k_fill() {
    int i = blockIdx.x * blockDim.x + threadIdx.x;
    if (i >= EE) return;
    int d = g_dst[i];
    int p = g_off[d] + atomicAdd(&g_fill[d], 1);
    g_csr[p] = g_src[i];
}

// ------------------- copy x into xcat[:, 0:128] -------------------
__global__ void k_copyx(const float* __restrict__ x) {
    int i = blockIdx.x * blockDim.x + threadIdx.x;
    if (i >= NN * DD) return;
    g_xcat[(size_t)(i >> 7) * XW + (i & 127)] = x[i];
}

// ------------------- prep: LayerNorm + SiLU, transposed outputs -------------------
template<int W, int RPB>
__global__ void __launch_bounds__(256) k_prep(int colOff,
                                              const float* __restrict__ lng,
                                              const float* __restrict__ lnb) {
    __shared__ float xs[RPB][W + 1];
    __shared__ float ss[RPB][W + 1];
    int warp = threadIdx.x >> 5, lane = threadIdx.x & 31;
    const int RPW = RPB / 8;
    #pragma unroll
    for (int rr = 0; rr < RPW; rr++) {
        int r = warp * RPW + rr;
        int gr = blockIdx.x * RPB + r;
        if (gr < NN) {
            float v[W / 32];
            float s = 0.f;
            #pragma unroll
            for (int j = 0; j < W / 32; j++) {
                v[j] = g_xcat[(size_t)gr * XW + colOff + lane + j * 32];
                s += v[j];
            }
            #pragma unroll
            for (int o = 16; o; o >>= 1) s += __shfl_xor_sync(0xffffffffu, s, o);
            float mean = s * (1.0f / W);
            float q = 0.f;
            #pragma unroll
            for (int j = 0; j < W / 32; j++) { float d = v[j] - mean; q += d * d; }
            #pragma unroll
            for (int o = 16; o; o >>= 1) q += __shfl_xor_sync(0xffffffffu, q, o);
            float rstd = rsqrtf(q * (1.0f / W) + 1e-5f);
            #pragma unroll
            for (int j = 0; j < W / 32; j++) {
                int c = lane + j * 32;
                xs[r][c] = (v[j] - mean) * rstd * lng[c] + lnb[c];
                ss[r][c] = v[j] / (1.0f + __expf(-v[j]));
            }
        }
    }
    __syncthreads();
    const int LG = (RPB == 32) ? 5 : 3;
    int base = blockIdx.x * RPB;
    #pragma unroll 4
    for (int idx = threadIdx.x; idx < RPB * W; idx += 256) {
        int r = idx & (RPB - 1);
        int d = idx >> LG;
        int gr = base + r;
        if (gr < NN) {
            g_XNT[(size_t)d * NN + gr] = xs[r][d];
            g_ST [(size_t)d * NN + gr] = ss[r][d];
        }
    }
}

// ------------------- weight prep -> bf16 hi/lo, chunked [chunk][n][kloc] -------------------
__global__ void k_prepWB(const float* __restrict__ sw, const float* __restrict__ bw) {
    int i = blockIdx.x * blockDim.x + threadIdx.x;
    if (i >= 640 * 128) return;
    int k = i >> 7, n = i & 127;
    float v = (k < 512) ? sw[n * 512 + k] : bw[n * 128 + (k - 512)];
    unsigned short h; asm("cvt.rn.bf16.f32 %0, %1;" : "=h"(h) : "f"(v));
    float vl = v - __uint_as_float(((uint32_t)h) << 16);
    unsigned short l; asm("cvt.rn.bf16.f32 %0, %1;" : "=h"(l) : "f"(vl));
    int c = k >> 5, kl = k & 31;
    int off = (c * 128 + n) * 32 + kl;
    g_WBh[off] = h;
    g_WBl[off] = l;
}
__global__ void k_prepWO(const float* __restrict__ swo, const float* __restrict__ bwo) {
    int i = blockIdx.x * blockDim.x + threadIdx.x;
    if (i >= 2560 * 64) return;
    int k = i >> 6, n = i & 63;
    float v = 0.0f;
    if (n < CC) v = (k < 2048) ? swo[n * 2048 + k] : bwo[n * 512 + (k - 2048)];
    unsigned short h; asm("cvt.rn.bf16.f32 %0, %1;" : "=h"(h) : "f"(v));
    float vl = v - __uint_as_float(((uint32_t)h) << 16);
    unsigned short l; asm("cvt.rn.bf16.f32 %0, %1;" : "=h"(l) : "f"(vl));
    int c = k >> 5, kl = k & 31;
    int off = (c * 64 + n) * 32 + kl;
    g_WOh[off] = h;
    g_WOl[off] = l;
}

// ------------------- A-chunk generation into padded SMEM (bf16 hi/lo) -------------------
// thread: row r (0..127), kh (0/1) handles k-range [kh*16, kh*16+16) of the 32-wide chunk
__device__ __forceinline__ void gen_basis(unsigned short* Ah, unsigned short* Al,
                                          int r, int kh, int bm, int d0) {
    #pragma unroll
    for (int jp = 0; jp < 2; jp++) {
        uint32_t hv[4], lv[4];
        #pragma unroll
        for (int dd = 0; dd < 2; dd++) {
            int dim = d0 + kh * 4 + jp * 2 + dd;
            float xn = g_XNT[(size_t)dim * NN + bm + r];
            float z0 = (xn + 2.0f) * 0.75f;
            float z1 = (xn + 0.66666667f) * 0.75f;
            float z2 = (xn - 0.66666667f) * 0.75f;
            float z3 = (xn - 2.0f) * 0.75f;
            float e0 = __expf(-z0 * z0), e1 = __expf(-z1 * z1);
            float e2 = __expf(-z2 * z2), e3 = __expf(-z3 * z3);
            uint32_t h01 = pkbf(e0, e1), h23 = pkbf(e2, e3);
            hv[dd * 2 + 0] = h01;
            hv[dd * 2 + 1] = h23;
            lv[dd * 2 + 0] = pkbf(e0 - lo2f(h01), e1 - hi2f(h01));
            lv[dd * 2 + 1] = pkbf(e2 - lo2f(h23), e3 - hi2f(h23));
        }
        int kb = kh * 16 + jp * 8;
        *(uint4*)&Ah[r * LSTR + kb] = make_uint4(hv[0], hv[1], hv[2], hv[3]);
        *(uint4*)&Al[r * LSTR + kb] = make_uint4(lv[0], lv[1], lv[2], lv[3]);
    }
}
__device__ __forceinline__ void gen_silu(unsigned short* Ah, unsigned short* Al,
                                         int r, int kh, int bm, int sd0) {
    #pragma unroll
    for (int q = 0; q < 2; q++) {
        uint32_t hv[4], lv[4];
        #pragma unroll
        for (int p = 0; p < 4; p++) {
            int sd = sd0 + kh * 16 + q * 8 + 2 * p;
            float v0 = g_ST[(size_t)sd * NN + bm + r];
            float v1 = g_ST[(size_t)(sd + 1) * NN + bm + r];
            uint32_t h = pkbf(v0, v1);
            hv[p] = h;
            lv[p] = pkbf(v0 - lo2f(h), v1 - hi2f(h));
        }
        int kb = kh * 16 + q * 8;
        *(uint4*)&Ah[r * LSTR + kb] = make_uint4(hv[0], hv[1], hv[2], hv[3]);
        *(uint4*)&Al[r * LSTR + kb] = make_uint4(lv[0], lv[1], lv[2], lv[3]);
    }
}

// ------------------- layer GEMM (mma.sync): h1[N,128] = [Basis|SiLU] @ W^T + bb ---------
__global__ void __launch_bounds__(256) k_mma_layer(const float* __restrict__ bb) {
    __shared__ __align__(16) unsigned short Ah[128 * LSTR], Al[128 * LSTR];
    __shared__ __align__(16) unsigned short Bh[128 * LSTR], Bl[128 * LSTR];
    int tid = threadIdx.x, lane = tid & 31, w = tid >> 5;
    int bm = blockIdx.x * 128;
    int r = tid & 127, kh = tid >> 7;
    int m0 = (w & 3) * 32, n0 = (w >> 2) * 64;

    float acc[2][8][4];
    #pragma unroll
    for (int a = 0; a < 2; a++)
        #pragma unroll
        for (int b = 0; b < 8; b++)
            #pragma unroll
            for (int c = 0; c < 4; c++) acc[a][b][c] = 0.f;

    uint32_t aAh = smem_u32(Ah), aAl = smem_u32(Al);
    uint32_t aBh = smem_u32(Bh), aBl = smem_u32(Bl);
    uint32_t offA = (((m0 + (lane & 15)) * LSTR) + ((lane >> 4) * 8)) * 2;
    uint32_t offB = (((n0 + (lane & 7) + ((lane & 16) ? 8 : 0)) * LSTR) + (((lane >> 3) & 1) * 8)) * 2;

    for (int c = 0; c < 20; c++) {
        if (c < 16) gen_basis(Ah, Al, r, kh, bm, c * 8);
        else        gen_silu (Ah, Al, r, kh, bm, (c - 16) * 32);
        {
            const uint4* sh = (const uint4*)g_WBh + c * 512;
            const uint4* sl = (const uint4*)g_WBl + c * 512;
            #pragma unroll
            for (int i2 = 0; i2 < 2; i2++) {
                int i = tid + i2 * 256;
                int n = i >> 2, kq = i & 3;
                *(uint4*)&Bh[n * LSTR + kq * 8] = sh[i];
                *(uint4*)&Bl[n * LSTR + kq * 8] = sl[i];
            }
        }
        __syncthreads();
        #pragma unroll
        for (int ks = 0; ks < 2; ks++) {
            uint32_t kadd = ks * 32;   // 16 bf16 = 32 bytes
            uint32_t ah[2][4], al[2][4];
            ldsm4(ah[0][0], ah[0][1], ah[0][2], ah[0][3], aAh + offA + kadd);
            ldsm4(ah[1][0], ah[1][1], ah[1][2], ah[1][3], aAh + offA + kadd + 16 * LSTR * 2);
            ldsm4(al[0][0], al[0][1], al[0][2], al[0][3], aAl + offA + kadd);
            ldsm4(al[1][0], al[1][1], al[1][2], al[1][3], aAl + offA + kadd + 16 * LSTR * 2);
            #pragma unroll
            for (int p = 0; p < 4; p++) {
                uint32_t bh[4], bl[4];
                uint32_t po = (uint32_t)(p * 16 * LSTR * 2);
                ldsm4(bh[0], bh[1], bh[2], bh[3], aBh + offB + kadd + po);
                ldsm4(bl[0], bl[1], bl[2], bl[3], aBl + offB + kadd + po);
                #pragma unroll
                for (int mf = 0; mf < 2; mf++) {
                    mmabf(acc[mf][2 * p],     ah[mf], bh[0], bh[1]);
                    mmabf(acc[mf][2 * p],     ah[mf], bl[0], bl[1]);
                    mmabf(acc[mf][2 * p],     al[mf], bh[0], bh[1]);
                    mmabf(acc[mf][2 * p + 1], ah[mf], bh[2], bh[3]);
                    mmabf(acc[mf][2 * p + 1], ah[mf], bl[2], bl[3]);
                    mmabf(acc[mf][2 * p + 1], al[mf], bh[2], bh[3]);
                }
            }
        }
        __syncthreads();
    }
    int gid = lane >> 2, tig = lane & 3;
    #pragma unroll
    for (int mf = 0; mf < 2; mf++) {
        #pragma unroll
        for (int nf = 0; nf < 8; nf++) {
            int col = n0 + nf * 8 + tig * 2;
            int row = bm + m0 + mf * 16 + gid;
            if (row < NN) {
                float2 v = make_float2(acc[mf][nf][0] + bb[col], acc[mf][nf][1] + bb[col + 1]);
                *(float2*)&g_h1[(size_t)row * HH + col] = v;
            }
            if (row + 8 < NN) {
                float2 v = make_float2(acc[mf][nf][2] + bb[col], acc[mf][nf][3] + bb[col + 1]);
                *(float2*)&g_h1[(size_t)(row + 8) * HH + col] = v;
            }
        }
    }
}

// ------------------- output GEMM (mma.sync): out[N,40] = [Basis|SiLU] @ Wo^T + bb ---------
__global__ void __launch_bounds__(256) k_mma_out(const float* __restrict__ bbo,
                                                 float* __restrict__ out) {
    __shared__ __align__(16) unsigned short Ah[128 * LSTR], Al[128 * LSTR];
    __shared__ __align__(16) unsigned short Bh[64 * LSTR], Bl[64 * LSTR];
    int tid = threadIdx.x, lane = tid & 31, w = tid >> 5;
    int bm = blockIdx.x * 128;
    int r = tid & 127, kh = tid >> 7;
    int m0 = (w & 3) * 32, n0 = (w >> 2) * 32;

    float acc[2][4][4];
    #pragma unroll
    for (int a = 0; a < 2; a++)
        #pragma unroll
        for (int b = 0; b < 4; b++)
            #pragma unroll
            for (int c = 0; c < 4; c++) acc[a][b][c] = 0.f;

    uint32_t aAh = smem_u32(Ah), aAl = smem_u32(Al);
    uint32_t aBh = smem_u32(Bh), aBl = smem_u32(Bl);
    uint32_t offA = (((m0 + (lane & 15)) * LSTR) + ((lane >> 4) * 8)) * 2;
    uint32_t offB = (((n0 + (lane & 7) + ((lane & 16) ? 8 : 0)) * LSTR) + (((lane >> 3) & 1) * 8)) * 2;

    for (int c = 0; c < 80; c++) {
        if (c < 64) gen_basis(Ah, Al, r, kh, bm, c * 8);
        else        gen_silu (Ah, Al, r, kh, bm, (c - 64) * 32);
        {
            const uint4* sh = (const uint4*)g_WOh + c * 256;
            const uint4* sl = (const uint4*)g_WOl + c * 256;
            int n = tid >> 2, kq = tid & 3;
            *(uint4*)&Bh[n * LSTR + kq * 8] = sh[tid];
            *(uint4*)&Bl[n * LSTR + kq * 8] = sl[tid];
        }
        __syncthreads();
        #pragma unroll
        for (int ks = 0; ks < 2; ks++) {
            uint32_t kadd = ks * 32;
            uint32_t ah[2][4], al[2][4];
            ldsm4(ah[0][0], ah[0][1], ah[0][2], ah[0][3], aAh + offA + kadd);
            ldsm4(ah[1][0], ah[1][1], ah[1][2], ah[1][3], aAh + offA + kadd + 16 * LSTR * 2);
            ldsm4(al[0][0], al[0][1], al[0][2], al[0][3], aAl + offA + kadd);
            ldsm4(al[1][0], al[1][1], al[1][2], al[1][3], aAl + offA + kadd + 16 * LSTR * 2);
            #pragma unroll
            for (int p = 0; p < 2; p++) {
                uint32_t bh[4], bl[4];
                uint32_t po = (uint32_t)(p * 16 * LSTR * 2);
                ldsm4(bh[0], bh[1], bh[2], bh[3], aBh + offB + kadd + po);
                ldsm4(bl[0], bl[1], bl[2], bl[3], aBl + offB + kadd + po);
                #pragma unroll
                for (int mf = 0; mf < 2; mf++) {
                    mmabf(acc[mf][2 * p],     ah[mf], bh[0], bh[1]);
                    mmabf(acc[mf][2 * p],     ah[mf], bl[0], bl[1]);
                    mmabf(acc[mf][2 * p],     al[mf], bh[0], bh[1]);
                    mmabf(acc[mf][2 * p + 1], ah[mf], bh[2], bh[3]);
                    mmabf(acc[mf][2 * p + 1], ah[mf], bl[2], bl[3]);
                    mmabf(acc[mf][2 * p + 1], al[mf], bh[2], bh[3]);
                }
            }
        }
        __syncthreads();
    }
    int gid = lane >> 2, tig = lane & 3;
    #pragma unroll
    for (int mf = 0; mf < 2; mf++) {
        #pragma unroll
        for (int nf = 0; nf < 4; nf++) {
            int col = n0 + nf * 8 + tig * 2;
            if (col >= CC) continue;
            int row = bm + m0 + mf * 16 + gid;
            if (row < NN) {
                float2 v = make_float2(acc[mf][nf][0] + bbo[col], acc[mf][nf][1] + bbo[col + 1]);
                *(float2*)&out[(size_t)row * CC + col] = v;
            }
            if (row + 8 < NN) {
                float2 v = make_float2(acc[mf][nf][2] + bbo[col], acc[mf][nf][3] + bbo[col + 1]);
                *(float2*)&out[(size_t)(row + 8) * CC + col] = v;
            }
        }
    }
}

// ------------------- GCN aggregation (pull via CSR, no atomics) -------------------
__global__ void __launch_bounds__(256) k_gcn() {
    int warp = blockIdx.x * 8 + (threadIdx.x >> 5);
    if (warp >= NN) return;
    int l = threadIdx.x & 31;
    float dn = g_dis[warp];
    float4 acc = make_float4(0.f, 0.f, 0.f, 0.f);
    int lo = g_off[warp], hi = g_off[warp + 1];
    for (int e = lo; e < hi; e++) {
        int sidx = g_csr[e];
        float wgt = g_dis[sidx];
        float4 hv = *(const float4*)(g_h1 + (size_t)sidx * HH + l * 4);
        acc.x += wgt * hv.x; acc.y += wgt * hv.y;
        acc.z += wgt * hv.z; acc.w += wgt * hv.w;
    }
    float4 self = *(const float4*)(g_h1 + (size_t)warp * HH + l * 4);
    float dn2 = dn * dn;
    float4 rr;
    rr.x = dn * acc.x + dn2 * self.x;
    rr.y = dn * acc.y + dn2 * self.y;
    rr.z = dn * acc.z + dn2 * self.z;
    rr.w = dn * acc.w + dn2 * self.w;
    *(float4*)(g_h2 + (size_t)warp * HH + l * 4) = rr;
}

// ------------------- BatchNorm -------------------
__global__ void k_zero_stats() {
    int t = threadIdx.x;
    g_sum[t] = 0.0; g_sumsq[t] = 0.0;
}
__global__ void __launch_bounds__(128) k_bn_partial() {
    int t = threadIdx.x;
    int r0 = blockIdx.x * 64;
    float s = 0.f, s2 = 0.f;
    #pragma unroll 4
    for (int r = 0; r < 64; r++) {
        int row = r0 + r;
        if (row < NN) {
            float v = g_h2[(size_t)row * HH + t];
            s += v; s2 += v * v;
        }
    }
    atomicAdd(&g_sum[t], (double)s);
    atomicAdd(&g_sumsq[t], (double)s2);
}
__global__ void k_bn_finalize(const float* __restrict__ bng, const float* __restrict__ bnb) {
    int t = threadIdx.x;
    double m = g_sum[t] / (double)NN;
    double var = g_sumsq[t] / (double)NN - m * m;
    float sc = bng[t] * rsqrtf((float)var + 1e-5f);
    g_bns[t] = sc;
    g_bnb[t] = bnb[t] - (float)m * sc;
}
__global__ void k_bn_apply(int layer) {
    int i = blockIdx.x * blockDim.x + threadIdx.x;
    if (i >= NN * HH) return;
    int c = i & 127;
    int n = i >> 7;
    g_xcat[(size_t)n * XW + DD + layer * HH + c] = g_h2[i] * g_bns[c] + g_bnb[c];
}

// ------------------- launch -------------------
extern "C" void kernel_launch(void* const* d_in, const int* in_sizes, int n_in,
                              void* d_out, int out_size) {
    const float* x      = (const float*)d_in[0];
    const void*  eidx   = d_in[1];
    const float* ln_g   = (const float*)d_in[2];
    const float* ln_b   = (const float*)d_in[3];
    const float* sw     = (const float*)d_in[4];
    const float* bw     = (const float*)d_in[5];
    const float* bb     = (const float*)d_in[6];
    // d_in[7] = gcn_bias: cancelled exactly by the following BatchNorm -> skipped
    const float* bn_g   = (const float*)d_in[8];
    const float* bn_b   = (const float*)d_in[9];
    const float* ln_go  = (const float*)d_in[10];
    const float* ln_bo  = (const float*)d_in[11];
    const float* sw_o   = (const float*)d_in[12];
    const float* bw_o   = (const float*)d_in[13];
    const float* bb_o   = (const float*)d_in[14];
    float* out = (float*)d_out;

    // graph / CSR build
    k_detect<<<1, 1>>>((const unsigned*)eidx);
    k_decode<<<(EE + 255) / 256, 256>>>(eidx);
    k_zero_cnt<<<(NN + 255) / 256, 256>>>();
    k_histo<<<(EE + 255) / 256, 256>>>();
    k_dis<<<(NN + 255) / 256, 256>>>();
    k_scan<<<1, 1024>>>();
    k_fill<<<(EE + 255) / 256, 256>>>();

    k_copyx<<<(NN * DD + 255) / 256, 256>>>(x);

    const int GT = (NN + 127) / 128;  // 391 M-tiles

    for (int i = 0; i < LL; i++) {
        k_prep<128, 32><<<(NN + 31) / 32, 256>>>(i * 128, ln_g + i * DD, ln_b + i * DD);
        k_prepWB<<<(640 * 128 + 255) / 256, 256>>>(sw + (size_t)i * HH * 512,
                                                   bw + (size_t)i * HH * DD);
        k_mma_layer<<<GT, 256>>>(bb + i * HH);
        k_gcn<<<(NN + 7) / 8, 256>>>();
        k_zero_stats<<<1, 128>>>();
        k_bn_partial<<<(NN + 63) / 64, 128>>>();
        k_bn_finalize<<<1, 128>>>(bn_g + i * HH, bn_b + i * HH);
        k_bn_apply<<<(NN * HH + 255) / 256, 256>>>(i);
    }

    k_prep<512, 8><<<(NN + 7) / 8, 256>>>(0, ln_go, ln_bo);
    k_prepWO<<<(2560 * 64 + 255) / 256, 256>>>(sw_o, bw_o);
    k_mma_out<<<GT, 256>>>(bb_o, out);
}

// round 6
// speedup vs baseline: 2.1862x; 1.1650x over previous
#include <cuda_runtime.h>
#include <cstdint>

#define NN 50000
#define DD 128
#define HH 128
#define CC 40
#define LL 3
#define EE 800000
#define XW 512        // D + L*H
#define LSTR 40       // padded SMEM row stride in bf16 units (80 bytes)

typedef unsigned long long ull;

// ------------------- device scratch (static: no allocation) -------------------
__device__ int    g_flag;
__device__ int    g_src[EE];
__device__ int    g_dst[EE];
__device__ float  g_dis[NN];
__device__ int    g_cnt[NN];
__device__ int    g_off[NN + 1];
__device__ int    g_fill[NN];
__device__ int    g_csr[EE];
__device__ float  g_xcat[(size_t)NN * XW];
__device__ float  g_XNT[(size_t)512 * NN + 256];
__device__ float  g_ST [(size_t)512 * NN + 256];
__device__ float  g_h1[(size_t)NN * HH];     // pre-scaled by dis[row]
__device__ float  g_h2[(size_t)NN * HH];
__device__ unsigned short g_WBh[20 * 128 * 32];   // layer B bf16-hi  [chunk][n][k]
__device__ unsigned short g_WBl[20 * 128 * 32];
__device__ unsigned short g_WOh[80 * 40 * 32];    // output B bf16-hi [chunk][n][k]
__device__ unsigned short g_WOl[80 * 40 * 32];
__device__ double g_sum[HH];
__device__ double g_sumsq[HH];
__device__ float  g_bns[HH];
__device__ float  g_bnb[HH];

// ------------------- helpers -------------------
__device__ __forceinline__ uint32_t smem_u32(const void* p) {
    uint32_t a;
    asm("{ .reg .u64 t; cvta.to.shared.u64 t, %1; cvt.u32.u64 %0, t; }" : "=r"(a) : "l"(p));
    return a;
}
__device__ __forceinline__ uint32_t pkbf(float a, float b) {   // [bf16(a) lo16 | bf16(b) hi16]
    uint32_t r;
    asm("cvt.rn.bf16x2.f32 %0, %1, %2;" : "=r"(r) : "f"(b), "f"(a));
    return r;
}
__device__ __forceinline__ float lo2f(uint32_t v) { return __uint_as_float(v << 16); }
__device__ __forceinline__ float hi2f(uint32_t v) { return __uint_as_float(v & 0xffff0000u); }

__device__ __forceinline__ void ldsm4(uint32_t& r0, uint32_t& r1, uint32_t& r2, uint32_t& r3,
                                      uint32_t a) {
    asm volatile("ldmatrix.sync.aligned.m8n8.x4.shared.b16 {%0,%1,%2,%3}, [%4];"
                 : "=r"(r0), "=r"(r1), "=r"(r2), "=r"(r3) : "r"(a));
}
__device__ __forceinline__ void ldsm2(uint32_t& r0, uint32_t& r1, uint32_t a) {
    asm volatile("ldmatrix.sync.aligned.m8n8.x2.shared.b16 {%0,%1}, [%2];"
                 : "=r"(r0), "=r"(r1) : "r"(a));
}
__device__ __forceinline__ void mmabf(float* c, const uint32_t* a, uint32_t b0, uint32_t b1) {
    asm volatile("mma.sync.aligned.m16n8k16.row.col.f32.bf16.bf16.f32 "
                 "{%0,%1,%2,%3}, {%4,%5,%6,%7}, {%8,%9}, {%0,%1,%2,%3};"
                 : "+f"(c[0]), "+f"(c[1]), "+f"(c[2]), "+f"(c[3])
                 : "r"(a[0]), "r"(a[1]), "r"(a[2]), "r"(a[3]), "r"(b0), "r"(b1));
}

// split one float into bf16 hi/lo pair packs
__device__ __forceinline__ void hilo2(float v0, float v1, uint32_t& h, uint32_t& l) {
    h = pkbf(v0, v1);
    l = pkbf(v0 - lo2f(h), v1 - hi2f(h));
}

// ------------------- edge dtype detect + decode -------------------
__global__ void k_detect(const unsigned* e) {
    int z = 0;
    for (int i = 0; i < 16; i++) z += (e[2 * i + 1] == 0u) ? 1 : 0;
    g_flag = (z == 16) ? 1 : 0;
}
__global__ void k_decode(const void* ep) {
    int i = blockIdx.x * blockDim.x + threadIdx.x;
    if (i >= EE) return;
    if (g_flag) {
        const long long* e = (const long long*)ep;
        g_src[i] = (int)e[i];
        g_dst[i] = (int)e[EE + i];
    } else {
        const int* e = (const int*)ep;
        g_src[i] = e[i];
        g_dst[i] = e[EE + i];
    }
}

// ------------------- degree / CSR build -------------------
__global__ void k_zero_cnt() {
    int i = blockIdx.x * blockDim.x + threadIdx.x;
    if (i < NN) { g_cnt[i] = 0; g_fill[i] = 0; }
}
__global__ void k_histo() {
    int i = blockIdx.x * blockDim.x + threadIdx.x;
    if (i < EE) atomicAdd(&g_cnt[g_dst[i]], 1);
}
__global__ void k_dis() {
    int i = blockIdx.x * blockDim.x + threadIdx.x;
    if (i < NN) g_dis[i] = rsqrtf((float)(g_cnt[i] + 1));
}
__global__ void k_scan() {
    __shared__ int ps[1024];
    int t = threadIdx.x;
    const int CH = (NN + 1023) / 1024;
    int lo = t * CH;
    int hi = lo + CH; if (hi > NN) hi = NN;
    if (lo > NN) lo = NN;
    int s = 0;
    for (int i = lo; i < hi; i++) s += g_cnt[i];
    ps[t] = s;
    __syncthreads();
    for (int d = 1; d < 1024; d <<= 1) {
        int v = (t >= d) ? ps[t - d] : 0;
        __syncthreads();
        ps[t] += v;
        __syncthreads();
    }
    int run = t ? ps[t - 1] : 0;
    for (int i = lo; i < hi; i++) { g_off[i] = run; run += g_cnt[i]; }
    if (t == 1023) g_off[NN] = run;
}
__global__ void k_fill() {
    int i = blockIdx.x * blockDim.x + threadIdx.x;
    if (i >= EE) return;
    int d = g_dst[i];
    int p = g_off[d] + atomicAdd(&g_fill[d], 1);
    g_csr[p] = g_src[i];
}

// ------------------- copy x into xcat[:, 0:128] -------------------
__global__ void k_copyx(const float* __restrict__ x) {
    int i = blockIdx.x * blockDim.x + threadIdx.x;
    if (i >= NN * DD) return;
    g_xcat[(size_t)(i >> 7) * XW + (i & 127)] = x[i];
}

// ------------------- prep: LayerNorm + SiLU, transposed outputs -------------------
template<int W, int RPB>
__global__ void __launch_bounds__(256) k_prep(int colOff,
                                              const float* __restrict__ lng,
                                              const float* __restrict__ lnb) {
    __shared__ float xs[RPB][W + 1];
    __shared__ float ss[RPB][W + 1];
    int warp = threadIdx.x >> 5, lane = threadIdx.x & 31;
    const int RPW = RPB / 8;
    #pragma unroll
    for (int rr = 0; rr < RPW; rr++) {
        int r = warp * RPW + rr;
        int gr = blockIdx.x * RPB + r;
        if (gr < NN) {
            float v[W / 32];
            float s = 0.f;
            #pragma unroll
            for (int j = 0; j < W / 32; j++) {
                v[j] = g_xcat[(size_t)gr * XW + colOff + lane + j * 32];
                s += v[j];
            }
            #pragma unroll
            for (int o = 16; o; o >>= 1) s += __shfl_xor_sync(0xffffffffu, s, o);
            float mean = s * (1.0f / W);
            float q = 0.f;
            #pragma unroll
            for (int j = 0; j < W / 32; j++) { float d = v[j] - mean; q += d * d; }
            #pragma unroll
            for (int o = 16; o; o >>= 1) q += __shfl_xor_sync(0xffffffffu, q, o);
            float rstd = rsqrtf(q * (1.0f / W) + 1e-5f);
            #pragma unroll
            for (int j = 0; j < W / 32; j++) {
                int c = lane + j * 32;
                xs[r][c] = (v[j] - mean) * rstd * lng[c] + lnb[c];
                ss[r][c] = v[j] / (1.0f + __expf(-v[j]));
            }
        }
    }
    __syncthreads();
    const int LG = (RPB == 32) ? 5 : 3;
    int base = blockIdx.x * RPB;
    #pragma unroll 4
    for (int idx = threadIdx.x; idx < RPB * W; idx += 256) {
        int r = idx & (RPB - 1);
        int d = idx >> LG;
        int gr = base + r;
        if (gr < NN) {
            g_XNT[(size_t)d * NN + gr] = xs[r][d];
            g_ST [(size_t)d * NN + gr] = ss[r][d];
        }
    }
}

// ------------------- weight prep -> bf16 hi/lo, chunked [chunk][n][kloc] -------------------
__global__ void k_prepWB(const float* __restrict__ sw, const float* __restrict__ bw) {
    int i = blockIdx.x * blockDim.x + threadIdx.x;
    if (i >= 640 * 128) return;
    int k = i >> 7, n = i & 127;
    float v = (k < 512) ? sw[n * 512 + k] : bw[n * 128 + (k - 512)];
    unsigned short h; asm("cvt.rn.bf16.f32 %0, %1;" : "=h"(h) : "f"(v));
    float vl = v - __uint_as_float(((uint32_t)h) << 16);
    unsigned short l; asm("cvt.rn.bf16.f32 %0, %1;" : "=h"(l) : "f"(vl));
    int c = k >> 5, kl = k & 31;
    int off = (c * 128 + n) * 32 + kl;
    g_WBh[off] = h;
    g_WBl[off] = l;
}
__global__ void k_prepWO(const float* __restrict__ swo, const float* __restrict__ bwo) {
    int i = blockIdx.x * blockDim.x + threadIdx.x;
    if (i >= 2560 * 40) return;
    int k = i / 40, n = i % 40;
    float v = (k < 2048) ? swo[n * 2048 + k] : bwo[n * 512 + (k - 2048)];
    unsigned short h; asm("cvt.rn.bf16.f32 %0, %1;" : "=h"(h) : "f"(v));
    float vl = v - __uint_as_float(((uint32_t)h) << 16);
    unsigned short l; asm("cvt.rn.bf16.f32 %0, %1;" : "=h"(l) : "f"(vl));
    int c = k >> 5, kl = k & 31;
    int off = c * 1280 + n * 32 + kl;
    g_WOh[off] = h;
    g_WOl[off] = l;
}

// ------------------- A-chunk store from prefetched regs (bf16 hi/lo, padded rows) -------------------
// thread: row r (0..127), kh (0/1) -> k-range [kh*16, kh*16+16)
__device__ __forceinline__ void store_basis(char* aAh, char* aAl, const float* pv, int r, int kh) {
    #pragma unroll
    for (int jp = 0; jp < 2; jp++) {
        uint32_t hv[4], lv[4];
        #pragma unroll
        for (int dd = 0; dd < 2; dd++) {
            float xn = pv[jp * 2 + dd];
            float z0 = (xn + 2.0f) * 0.75f;
            float z1 = (xn + 0.66666667f) * 0.75f;
            float z2 = (xn - 0.66666667f) * 0.75f;
            float z3 = (xn - 2.0f) * 0.75f;
            float e0 = __expf(-z0 * z0), e1 = __expf(-z1 * z1);
            float e2 = __expf(-z2 * z2), e3 = __expf(-z3 * z3);
            hilo2(e0, e1, hv[dd * 2 + 0], lv[dd * 2 + 0]);
            hilo2(e2, e3, hv[dd * 2 + 1], lv[dd * 2 + 1]);
        }
        int kb = kh * 16 + jp * 8;
        *(uint4*)(aAh + (r * LSTR + kb) * 2) = make_uint4(hv[0], hv[1], hv[2], hv[3]);
        *(uint4*)(aAl + (r * LSTR + kb) * 2) = make_uint4(lv[0], lv[1], lv[2], lv[3]);
    }
}
__device__ __forceinline__ void store_silu(char* aAh, char* aAl, const float* pv, int r, int kh) {
    #pragma unroll
    for (int q = 0; q < 2; q++) {
        uint32_t hv[4], lv[4];
        #pragma unroll
        for (int p = 0; p < 4; p++)
            hilo2(pv[q * 8 + 2 * p], pv[q * 8 + 2 * p + 1], hv[p], lv[p]);
        int kb = kh * 16 + q * 8;
        *(uint4*)(aAh + (r * LSTR + kb) * 2) = make_uint4(hv[0], hv[1], hv[2], hv[3]);
        *(uint4*)(aAl + (r * LSTR + kb) * 2) = make_uint4(lv[0], lv[1], lv[2], lv[3]);
    }
}

// ------------------- layer GEMM (pipelined): h1[N,128] = dis*( [Basis|SiLU] @ W^T + bb ) ------
__global__ void __launch_bounds__(256) k_mma_layer(const float* __restrict__ bb) {
    extern __shared__ char sm[];
    const int BUF = 40960;   // Ah 10240 | Al 10240 | Bh 10240 | Bl 10240
    int tid = threadIdx.x, lane = tid & 31, w = tid >> 5;
    int bm = blockIdx.x * 128;
    int r = tid & 127, kh = tid >> 7;
    int m0 = (w & 3) * 32, n0 = (w >> 2) * 64;

    float acc[2][8][4];
    #pragma unroll
    for (int a = 0; a < 2; a++)
        #pragma unroll
        for (int b = 0; b < 8; b++)
            #pragma unroll
            for (int c = 0; c < 4; c++) acc[a][b][c] = 0.f;

    uint32_t sb = smem_u32(sm);
    uint32_t offA = ((m0 + (lane & 15)) * LSTR + (lane >> 4) * 8) * 2;
    uint32_t offB = ((n0 + (lane & 7) + ((lane & 16) ? 8 : 0)) * LSTR + ((lane >> 3) & 1) * 8) * 2;

    float pv[16];
    uint4 pbh[2], pbl[2];

    // prefetch chunk 0
    {
        int d0 = kh * 4;
        #pragma unroll
        for (int j = 0; j < 4; j++) pv[j] = g_XNT[(size_t)(d0 + j) * NN + bm + r];
        const uint4* sh = (const uint4*)g_WBh;
        const uint4* sl = (const uint4*)g_WBl;
        pbh[0] = sh[tid]; pbh[1] = sh[tid + 256];
        pbl[0] = sl[tid]; pbl[1] = sl[tid + 256];
    }

    for (int c = 0; c < 20; c++) {
        int cur = c & 1;
        char* base = sm + cur * BUF;
        if (c < 16) store_basis(base, base + 10240, pv, r, kh);
        else        store_silu (base, base + 10240, pv, r, kh);
        {
            int n = tid >> 2, kq = tid & 3;
            int i2 = tid + 256;
            int n2 = i2 >> 2, kq2 = i2 & 3;
            *(uint4*)(base + 20480 + (n * LSTR + kq * 8) * 2)  = pbh[0];
            *(uint4*)(base + 20480 + (n2 * LSTR + kq2 * 8) * 2) = pbh[1];
            *(uint4*)(base + 30720 + (n * LSTR + kq * 8) * 2)  = pbl[0];
            *(uint4*)(base + 30720 + (n2 * LSTR + kq2 * 8) * 2) = pbl[1];
        }
        __syncthreads();
        if (c < 19) {   // prefetch next chunk (LDG latency hidden behind mma below)
            int cn = c + 1;
            if (cn < 16) {
                int d0 = cn * 8 + kh * 4;
                #pragma unroll
                for (int j = 0; j < 4; j++) pv[j] = g_XNT[(size_t)(d0 + j) * NN + bm + r];
            } else {
                int sd0 = (cn - 16) * 32 + kh * 16;
                #pragma unroll
                for (int q = 0; q < 16; q++) pv[q] = g_ST[(size_t)(sd0 + q) * NN + bm + r];
            }
            const uint4* sh = (const uint4*)g_WBh + cn * 512;
            const uint4* sl = (const uint4*)g_WBl + cn * 512;
            pbh[0] = sh[tid]; pbh[1] = sh[tid + 256];
            pbl[0] = sl[tid]; pbl[1] = sl[tid + 256];
        }
        uint32_t aAh = sb + cur * BUF, aAl = aAh + 10240;
        uint32_t aBh = aAh + 20480,   aBl = aAh + 30720;
        #pragma unroll
        for (int ks = 0; ks < 2; ks++) {
            uint32_t kadd = ks * 32;
            uint32_t ah[2][4], al[2][4];
            ldsm4(ah[0][0], ah[0][1], ah[0][2], ah[0][3], aAh + offA + kadd);
            ldsm4(ah[1][0], ah[1][1], ah[1][2], ah[1][3], aAh + offA + kadd + 16 * LSTR * 2);
            ldsm4(al[0][0], al[0][1], al[0][2], al[0][3], aAl + offA + kadd);
            ldsm4(al[1][0], al[1][1], al[1][2], al[1][3], aAl + offA + kadd + 16 * LSTR * 2);
            #pragma unroll
            for (int p = 0; p < 4; p++) {
                uint32_t bh[4], bl[4];
                uint32_t po = (uint32_t)(p * 16 * LSTR * 2);
                ldsm4(bh[0], bh[1], bh[2], bh[3], aBh + offB + kadd + po);
                ldsm4(bl[0], bl[1], bl[2], bl[3], aBl + offB + kadd + po);
                #pragma unroll
                for (int mf = 0; mf < 2; mf++) {
                    mmabf(acc[mf][2 * p],     ah[mf], bh[0], bh[1]);
                    mmabf(acc[mf][2 * p],     ah[mf], bl[0], bl[1]);
                    mmabf(acc[mf][2 * p],     al[mf], bh[0], bh[1]);
                    mmabf(acc[mf][2 * p + 1], ah[mf], bh[2], bh[3]);
                    mmabf(acc[mf][2 * p + 1], ah[mf], bl[2], bl[3]);
                    mmabf(acc[mf][2 * p + 1], al[mf], bh[2], bh[3]);
                }
            }
        }
    }
    int gid = lane >> 2, tig = lane & 3;
    #pragma unroll
    for (int mf = 0; mf < 2; mf++) {
        int row = bm + m0 + mf * 16 + gid;
        float d0 = (row < NN) ? g_dis[row] : 0.f;
        float d1 = (row + 8 < NN) ? g_dis[row + 8] : 0.f;
        #pragma unroll
        for (int nf = 0; nf < 8; nf++) {
            int col = n0 + nf * 8 + tig * 2;
            if (row < NN) {
                float2 v = make_float2((acc[mf][nf][0] + bb[col]) * d0,
                                       (acc[mf][nf][1] + bb[col + 1]) * d0);
                *(float2*)&g_h1[(size_t)row * HH + col] = v;
            }
            if (row + 8 < NN) {
                float2 v = make_float2((acc[mf][nf][2] + bb[col]) * d1,
                                       (acc[mf][nf][3] + bb[col + 1]) * d1);
                *(float2*)&g_h1[(size_t)(row + 8) * HH + col] = v;
            }
        }
    }
}

// ------------------- output GEMM (pipelined, N=40): out = [Basis|SiLU] @ Wo^T + bb ---------
__global__ void __launch_bounds__(256) k_mma_out(const float* __restrict__ bbo,
                                                 float* __restrict__ out) {
    extern __shared__ char sm[];
    const int BUF = 26880;   // Ah 10240 | Al 10240 | Bh 3200 | Bl 3200
    int tid = threadIdx.x, lane = tid & 31, w = tid >> 5;
    int bm = blockIdx.x * 128;
    int r = tid & 127, kh = tid >> 7;
    int m0 = w * 16;

    float acc[5][4];
    #pragma unroll
    for (int b = 0; b < 5; b++)
        #pragma unroll
        for (int c = 0; c < 4; c++) acc[b][c] = 0.f;

    uint32_t sb = smem_u32(sm);
    uint32_t offA  = ((m0 + (lane & 15)) * LSTR + (lane >> 4) * 8) * 2;
    uint32_t offB  = (((lane & 7) + ((lane & 16) ? 8 : 0)) * LSTR + ((lane >> 3) & 1) * 8) * 2;
    uint32_t offB2 = ((32 + (lane & 7)) * LSTR + ((lane >> 3) & 1) * 8) * 2;

    float pv[16];
    uint4 pbh, pbl;

    // prefetch chunk 0
    {
        int d0 = kh * 4;
        #pragma unroll
        for (int j = 0; j < 4; j++) pv[j] = g_XNT[(size_t)(d0 + j) * NN + bm + r];
        if (tid < 160) {
            pbh = ((const uint4*)g_WOh)[tid];
            pbl = ((const uint4*)g_WOl)[tid];
        }
    }

    for (int c = 0; c < 80; c++) {
        int cur = c & 1;
        char* base = sm + cur * BUF;
        if (c < 64) store_basis(base, base + 10240, pv, r, kh);
        else        store_silu (base, base + 10240, pv, r, kh);
        if (tid < 160) {
            int n = tid >> 2, kq = tid & 3;
            *(uint4*)(base + 20480 + (n * LSTR + kq * 8) * 2) = pbh;
            *(uint4*)(base + 23680 + (n * LSTR + kq * 8) * 2) = pbl;
        }
        __syncthreads();
        if (c < 79) {
            int cn = c + 1;
            if (cn < 64) {
                int d0 = cn * 8 + kh * 4;
                #pragma unroll
                for (int j = 0; j < 4; j++) pv[j] = g_XNT[(size_t)(d0 + j) * NN + bm + r];
            } else {
                int sd0 = (cn - 64) * 32 + kh * 16;
                #pragma unroll
                for (int q = 0; q < 16; q++) pv[q] = g_ST[(size_t)(sd0 + q) * NN + bm + r];
            }
            if (tid < 160) {
                pbh = ((const uint4*)g_WOh + cn * 160)[tid];
                pbl = ((const uint4*)g_WOl + cn * 160)[tid];
            }
        }
        uint32_t aAh = sb + cur * BUF, aAl = aAh + 10240;
        uint32_t aBh = aAh + 20480,   aBl = aAh + 23680;
        #pragma unroll
        for (int ks = 0; ks < 2; ks++) {
            uint32_t kadd = ks * 32;
            uint32_t ah[4], al[4];
            ldsm4(ah[0], ah[1], ah[2], ah[3], aAh + offA + kadd);
            ldsm4(al[0], al[1], al[2], al[3], aAl + offA + kadd);
            #pragma unroll
            for (int g = 0; g < 2; g++) {
                uint32_t bh[4], bl[4];
                uint32_t po = (uint32_t)(g * 16 * LSTR * 2);
                ldsm4(bh[0], bh[1], bh[2], bh[3], aBh + offB + kadd + po);
                ldsm4(bl[0], bl[1], bl[2], bl[3], aBl + offB + kadd + po);
                mmabf(acc[2 * g],     ah, bh[0], bh[1]);
                mmabf(acc[2 * g],     ah, bl[0], bl[1]);
                mmabf(acc[2 * g],     al, bh[0], bh[1]);
                mmabf(acc[2 * g + 1], ah, bh[2], bh[3]);
                mmabf(acc[2 * g + 1], ah, bl[2], bl[3]);
                mmabf(acc[2 * g + 1], al, bh[2], bh[3]);
            }
            {
                uint32_t b0, b1, c0, c1;
                ldsm2(b0, b1, aBh + offB2 + kadd);
                ldsm2(c0, c1, aBl + offB2 + kadd);
                mmabf(acc[4], ah, b0, b1);
                mmabf(acc[4], ah, c0, c1);
                mmabf(acc[4], al, b0, b1);
            }
        }
    }
    int gid = lane >> 2, tig = lane & 3;
    int row = bm + m0 + gid;
    #pragma unroll
    for (int nf = 0; nf < 5; nf++) {
        int col = nf * 8 + tig * 2;
        if (row < NN) {
            float2 v = make_float2(acc[nf][0] + bbo[col], acc[nf][1] + bbo[col + 1]);
            *(float2*)&out[(size_t)row * CC + col] = v;
        }
        if (row + 8 < NN) {
            float2 v = make_float2(acc[nf][2] + bbo[col], acc[nf][3] + bbo[col + 1]);
            *(float2*)&out[(size_t)(row + 8) * CC + col] = v;
        }
    }
}

// ------------------- GCN aggregation (pull via CSR; h1 pre-scaled by dis) -------------------
__global__ void __launch_bounds__(256) k_gcn() {
    int warp = blockIdx.x * 8 + (threadIdx.x >> 5);
    if (warp >= NN) return;
    int l = threadIdx.x & 31;
    float dn = g_dis[warp];
    float4 acc = *(const float4*)(g_h1 + (size_t)warp * HH + l * 4);  // self term
    int lo = g_off[warp], hi = g_off[warp + 1];
    for (int e = lo; e < hi; e++) {
        int sidx = g_csr[e];
        float4 hv = *(const float4*)(g_h1 + (size_t)sidx * HH + l * 4);
        acc.x += hv.x; acc.y += hv.y; acc.z += hv.z; acc.w += hv.w;
    }
    float4 rr = make_float4(dn * acc.x, dn * acc.y, dn * acc.z, dn * acc.w);
    *(float4*)(g_h2 + (size_t)warp * HH + l * 4) = rr;
}

// ------------------- BatchNorm -------------------
__global__ void k_zero_stats() {
    int t = threadIdx.x;
    g_sum[t] = 0.0; g_sumsq[t] = 0.0;
}
__global__ void __launch_bounds__(128) k_bn_partial() {
    int t = threadIdx.x;
    int r0 = blockIdx.x * 64;
    float s = 0.f, s2 = 0.f;
    #pragma unroll 4
    for (int r = 0; r < 64; r++) {
        int row = r0 + r;
        if (row < NN) {
            float v = g_h2[(size_t)row * HH + t];
            s += v; s2 += v * v;
        }
    }
    atomicAdd(&g_sum[t], (double)s);
    atomicAdd(&g_sumsq[t], (double)s2);
}
__global__ void k_bn_finalize(const float* __restrict__ bng, const float* __restrict__ bnb) {
    int t = threadIdx.x;
    double m = g_sum[t] / (double)NN;
    double var = g_sumsq[t] / (double)NN - m * m;
    float sc = bng[t] * rsqrtf((float)var + 1e-5f);
    g_bns[t] = sc;
    g_bnb[t] = bnb[t] - (float)m * sc;
}
__global__ void k_bn_apply(int layer) {
    int i = blockIdx.x * blockDim.x + threadIdx.x;
    if (i >= NN * HH) return;
    int c = i & 127;
    int n = i >> 7;
    g_xcat[(size_t)n * XW + DD + layer * HH + c] = g_h2[i] * g_bns[c] + g_bnb[c];
}

// ------------------- launch -------------------
extern "C" void kernel_launch(void* const* d_in, const int* in_sizes, int n_in,
                              void* d_out, int out_size) {
    const float* x      = (const float*)d_in[0];
    const void*  eidx   = d_in[1];
    const float* ln_g   = (const float*)d_in[2];
    const float* ln_b   = (const float*)d_in[3];
    const float* sw     = (const float*)d_in[4];
    const float* bw     = (const float*)d_in[5];
    const float* bb     = (const float*)d_in[6];
    // d_in[7] = gcn_bias: cancelled exactly by the following BatchNorm -> skipped
    const float* bn_g   = (const float*)d_in[8];
    const float* bn_b   = (const float*)d_in[9];
    const float* ln_go  = (const float*)d_in[10];
    const float* ln_bo  = (const float*)d_in[11];
    const float* sw_o   = (const float*)d_in[12];
    const float* bw_o   = (const float*)d_in[13];
    const float* bb_o   = (const float*)d_in[14];
    float* out = (float*)d_out;

    const int SMEM_L = 2 * 40960;   // 81920
    const int SMEM_O = 2 * 26880;   // 53760
    cudaFuncSetAttribute(k_mma_layer, cudaFuncAttributeMaxDynamicSharedMemorySize, SMEM_L);
    cudaFuncSetAttribute(k_mma_out,   cudaFuncAttributeMaxDynamicSharedMemorySize, SMEM_O);

    // graph / CSR build
    k_detect<<<1, 1>>>((const unsigned*)eidx);
    k_decode<<<(EE + 255) / 256, 256>>>(eidx);
    k_zero_cnt<<<(NN + 255) / 256, 256>>>();
    k_histo<<<(EE + 255) / 256, 256>>>();
    k_dis<<<(NN + 255) / 256, 256>>>();
    k_scan<<<1, 1024>>>();
    k_fill<<<(EE + 255) / 256, 256>>>();

    k_copyx<<<(NN * DD + 255) / 256, 256>>>(x);

    const int GT = (NN + 127) / 128;  // 391 M-tiles

    for (int i = 0; i < LL; i++) {
        k_prep<128, 32><<<(NN + 31) / 32, 256>>>(i * 128, ln_g + i * DD, ln_b + i * DD);
        k_prepWB<<<(640 * 128 + 255) / 256, 256>>>(sw + (size_t)i * HH * 512,
                                                   bw + (size_t)i * HH * DD);
        k_mma_layer<<<GT, 256, SMEM_L>>>(bb + i * HH);
        k_gcn<<<(NN + 7) / 8, 256>>>();
        k_zero_stats<<<1, 128>>>();
        k_bn_partial<<<(NN + 63) / 64, 128>>>();
        k_bn_finalize<<<1, 128>>>(bn_g + i * HH, bn_b + i * HH);
        k_bn_apply<<<(NN * HH + 255) / 256, 256>>>(i);
    }

    k_prep<512, 8><<<(NN + 7) / 8, 256>>>(0, ln_go, ln_bo);
    k_prepWO<<<(2560 * 40 + 255) / 256, 256>>>(sw_o, bw_o);
    k_mma_out<<<GT, 256, SMEM_O>>>(bb_o, out);
}

// round 8
// speedup vs baseline: 2.4913x; 1.1395x over previous
#include <cuda_runtime.h>
#include <cstdint>

#define NN 50000
#define NP 50048      // padded node stride for transposed tensors
#define DD 128
#define HH 128
#define CC 40
#define LL 3
#define EE 800000
#define LSTR 40       // padded SMEM row stride in bf16 units (80 bytes)

// ------------------- device scratch (static: no allocation) -------------------
__device__ int    g_flag;
__device__ int    g_src[EE];
__device__ int    g_dst[EE];
__device__ float  g_dis[NN];
__device__ int    g_cnt[NN];
__device__ int    g_off[NN + 1];
__device__ int    g_fill[NN];
__device__ int    g_csr[EE];
__device__ float  g_XT[(size_t)512 * NP];    // transposed raw values [d][n]
__device__ float  g_mu[4][NP];               // per-LN-set node mean
__device__ float  g_rs[4][NP];               // per-LN-set node rstd
__device__ float  g_osum[NP];                // output-LN partial: sum over 512 dims
__device__ float  g_osq[NP];                 // output-LN partial: sumsq
__device__ float  g_h1[(size_t)NN * HH];     // pre-scaled by dis[row]
__device__ float  g_h2[(size_t)NN * HH];
__device__ unsigned short g_WBh[20 * 128 * 32];   // layer B bf16-hi [chunk][n][k]
__device__ unsigned short g_WBl[20 * 128 * 32];
__device__ unsigned short g_WOh[80 * 40 * 32];    // output B bf16-hi [chunk][n][k]
__device__ unsigned short g_WOl[80 * 40 * 32];
__device__ double g_sum[HH];
__device__ double g_sumsq[HH];
__device__ float  g_bns[HH];
__device__ float  g_bnb[HH];

// ------------------- helpers -------------------
__device__ __forceinline__ uint32_t smem_u32(const void* p) {
    uint32_t a;
    asm("{ .reg .u64 t; cvta.to.shared.u64 t, %1; cvt.u32.u64 %0, t; }" : "=r"(a) : "l"(p));
    return a;
}
__device__ __forceinline__ uint32_t pkbf(float a, float b) {   // [bf16(a) lo16 | bf16(b) hi16]
    uint32_t r;
    asm("cvt.rn.bf16x2.f32 %0, %1, %2;" : "=r"(r) : "f"(b), "f"(a));
    return r;
}
__device__ __forceinline__ float lo2f(uint32_t v) { return __uint_as_float(v << 16); }
__device__ __forceinline__ float hi2f(uint32_t v) { return __uint_as_float(v & 0xffff0000u); }

__device__ __forceinline__ void ldsm4(uint32_t& r0, uint32_t& r1, uint32_t& r2, uint32_t& r3,
                                      uint32_t a) {
    asm volatile("ldmatrix.sync.aligned.m8n8.x4.shared.b16 {%0,%1,%2,%3}, [%4];"
                 : "=r"(r0), "=r"(r1), "=r"(r2), "=r"(r3) : "r"(a));
}
__device__ __forceinline__ void ldsm2(uint32_t& r0, uint32_t& r1, uint32_t a) {
    asm volatile("ldmatrix.sync.aligned.m8n8.x2.shared.b16 {%0,%1}, [%2];"
                 : "=r"(r0), "=r"(r1) : "r"(a));
}
__device__ __forceinline__ void mmabf(float* c, const uint32_t* a, uint32_t b0, uint32_t b1) {
    asm volatile("mma.sync.aligned.m16n8k16.row.col.f32.bf16.bf16.f32 "
                 "{%0,%1,%2,%3}, {%4,%5,%6,%7}, {%8,%9}, {%0,%1,%2,%3};"
                 : "+f"(c[0]), "+f"(c[1]), "+f"(c[2]), "+f"(c[3])
                 : "r"(a[0]), "r"(a[1]), "r"(a[2]), "r"(a[3]), "r"(b0), "r"(b1));
}
__device__ __forceinline__ void hilo2(float v0, float v1, uint32_t& h, uint32_t& l) {
    h = pkbf(v0, v1);
    l = pkbf(v0 - lo2f(h), v1 - hi2f(h));
}
__device__ __forceinline__ float silu_f(float v) {
    return __fdividef(v, 1.0f + __expf(-v));
}

// ------------------- edge dtype detect + decode(+histogram) -------------------
__global__ void k_detect(const unsigned* e) {
    int z = 0;
    for (int i = 0; i < 16; i++) z += (e[2 * i + 1] == 0u) ? 1 : 0;
    g_flag = (z == 16) ? 1 : 0;
}
__global__ void k_zero_cnt() {
    int i = blockIdx.x * blockDim.x + threadIdx.x;
    if (i < NN) { g_cnt[i] = 0; g_fill[i] = 0; }
}
__global__ void k_decode(const void* ep) {
    int i = blockIdx.x * blockDim.x + threadIdx.x;
    if (i >= EE) return;
    int s, d;
    if (g_flag) {
        const long long* e = (const long long*)ep;
        s = (int)e[i];
        d = (int)e[EE + i];
    } else {
        const int* e = (const int*)ep;
        s = e[i];
        d = e[EE + i];
    }
    g_src[i] = s;
    g_dst[i] = d;
    atomicAdd(&g_cnt[d], 1);
}
__global__ void k_dis() {
    int i = blockIdx.x * blockDim.x + threadIdx.x;
    if (i < NN) g_dis[i] = rsqrtf((float)(g_cnt[i] + 1));
}
__global__ void k_scan() {
    __shared__ int ps[1024];
    int t = threadIdx.x;
    const int CH = (NN + 1023) / 1024;
    int lo = t * CH;
    int hi = lo + CH; if (hi > NN) hi = NN;
    if (lo > NN) lo = NN;
    int s = 0;
    for (int i = lo; i < hi; i++) s += g_cnt[i];
    ps[t] = s;
    __syncthreads();
    for (int d = 1; d < 1024; d <<= 1) {
        int v = (t >= d) ? ps[t - d] : 0;
        __syncthreads();
        ps[t] += v;
        __syncthreads();
    }
    int run = t ? ps[t - 1] : 0;
    for (int i = lo; i < hi; i++) { g_off[i] = run; run += g_cnt[i]; }
    if (t == 1023) g_off[NN] = run;
}
__global__ void k_fill() {
    int i = blockIdx.x * blockDim.x + threadIdx.x;
    if (i >= EE) return;
    int d = g_dst[i];
    int p = g_off[d] + atomicAdd(&g_fill[d], 1);
    g_csr[p] = g_src[i];
}

// ------------------- x transpose + LN0 stats + output-LN partial init -------------------
__global__ void __launch_bounds__(256) k_tx(const float* __restrict__ x) {
    __shared__ float xs[32][129];
    int warp = threadIdx.x >> 5, lane = threadIdx.x & 31;
    int base = blockIdx.x * 32;
    #pragma unroll
    for (int rr = 0; rr < 4; rr++) {
        int r = warp * 4 + rr;
        int gr = base + r;
        if (gr < NN) {
            float v[4];
            float s = 0.f, sq = 0.f;
            #pragma unroll
            for (int j = 0; j < 4; j++) {
                v[j] = x[(size_t)gr * DD + lane + j * 32];
                s += v[j]; sq += v[j] * v[j];
            }
            #pragma unroll
            for (int o = 16; o; o >>= 1) {
                s  += __shfl_xor_sync(0xffffffffu, s, o);
                sq += __shfl_xor_sync(0xffffffffu, sq, o);
            }
            #pragma unroll
            for (int j = 0; j < 4; j++) xs[r][lane + j * 32] = v[j];
            if (lane == 0) {
                float mean = s * (1.0f / 128.0f);
                float var = sq * (1.0f / 128.0f) - mean * mean;
                g_mu[0][gr] = mean;
                g_rs[0][gr] = rsqrtf(var + 1e-5f);
                g_osum[gr] = s;
                g_osq[gr]  = sq;
            }
        }
    }
    __syncthreads();
    #pragma unroll 4
    for (int idx = threadIdx.x; idx < 32 * 128; idx += 256) {
        int r = idx & 31, d = idx >> 5;
        int gr = base + r;
        if (gr < NN) g_XT[(size_t)d * NP + gr] = xs[r][d];
    }
}

// ------------------- BN apply + transpose into XT + next-LN stats + output-LN partials ----
__global__ void __launch_bounds__(256) k_bnt(int rowBase, int statSet) {
    __shared__ float xs[32][129];
    int warp = threadIdx.x >> 5, lane = threadIdx.x & 31;
    int base = blockIdx.x * 32;
    #pragma unroll
    for (int rr = 0; rr < 4; rr++) {
        int r = warp * 4 + rr;
        int gr = base + r;
        if (gr < NN) {
            float v[4];
            float s = 0.f, sq = 0.f;
            #pragma unroll
            for (int j = 0; j < 4; j++) {
                int c = lane + j * 32;
                v[j] = g_h2[(size_t)gr * HH + c] * g_bns[c] + g_bnb[c];
                s += v[j]; sq += v[j] * v[j];
            }
            #pragma unroll
            for (int o = 16; o; o >>= 1) {
                s  += __shfl_xor_sync(0xffffffffu, s, o);
                sq += __shfl_xor_sync(0xffffffffu, sq, o);
            }
            #pragma unroll
            for (int j = 0; j < 4; j++) xs[r][lane + j * 32] = v[j];
            if (lane == 0) {
                float mean = s * (1.0f / 128.0f);
                float var = sq * (1.0f / 128.0f) - mean * mean;
                g_mu[statSet][gr] = mean;
                g_rs[statSet][gr] = rsqrtf(var + 1e-5f);
                g_osum[gr] += s;
                g_osq[gr]  += sq;
            }
        }
    }
    __syncthreads();
    #pragma unroll 4
    for (int idx = threadIdx.x; idx < 32 * 128; idx += 256) {
        int r = idx & 31, d = idx >> 5;
        int gr = base + r;
        if (gr < NN) g_XT[(size_t)(rowBase + d) * NP + gr] = xs[r][d];
    }
}

// ------------------- weight prep -> bf16 hi/lo, chunked [chunk][n][kloc] -------------------
__global__ void k_prepWB(const float* __restrict__ sw, const float* __restrict__ bw, int li) {
    int i = blockIdx.x * blockDim.x + threadIdx.x;
    if (i >= 640 * 128) return;
    int k = i >> 7, n = i & 127;
    sw += (size_t)li * 128 * 512;
    bw += (size_t)li * 128 * 128;
    float v = (k < 512) ? sw[n * 512 + k] : bw[n * 128 + (k - 512)];
    unsigned short h; asm("cvt.rn.bf16.f32 %0, %1;" : "=h"(h) : "f"(v));
    float vl = v - __uint_as_float(((uint32_t)h) << 16);
    unsigned short l; asm("cvt.rn.bf16.f32 %0, %1;" : "=h"(l) : "f"(vl));
    int c = k >> 5, kl = k & 31;
    int off = (c * 128 + n) * 32 + kl;
    g_WBh[off] = h;
    g_WBl[off] = l;
}
__global__ void k_prepWO(const float* __restrict__ swo, const float* __restrict__ bwo) {
    int i = blockIdx.x * blockDim.x + threadIdx.x;
    if (i >= 2560 * 40) return;
    int k = i / 40, n = i % 40;
    float v = (k < 2048) ? swo[n * 2048 + k] : bwo[n * 512 + (k - 2048)];
    unsigned short h; asm("cvt.rn.bf16.f32 %0, %1;" : "=h"(h) : "f"(v));
    float vl = v - __uint_as_float(((uint32_t)h) << 16);
    unsigned short l; asm("cvt.rn.bf16.f32 %0, %1;" : "=h"(l) : "f"(vl));
    int c = k >> 5, kl = k & 31;
    int off = c * 1280 + n * 32 + kl;
    g_WOh[off] = h;
    g_WOl[off] = l;
}

// ------------------- A-chunk stores: LN+RBF or SiLU applied to prefetched raw values -----
__device__ __forceinline__ void store_basis(char* aAh, char* aAl, const float* pv,
                                            int r, int kh, float mu, float rs,
                                            const float* lg, const float* lb) {
    #pragma unroll
    for (int jp = 0; jp < 2; jp++) {
        uint32_t hv[4], lv[4];
        #pragma unroll
        for (int dd = 0; dd < 2; dd++) {
            int j = jp * 2 + dd;
            float xn = (pv[j] - mu) * rs * lg[j] + lb[j];
            float z0 = (xn + 2.0f) * 0.75f;
            float z1 = (xn + 0.66666667f) * 0.75f;
            float z2 = (xn - 0.66666667f) * 0.75f;
            float z3 = (xn - 2.0f) * 0.75f;
            float e0 = __expf(-z0 * z0), e1 = __expf(-z1 * z1);
            float e2 = __expf(-z2 * z2), e3 = __expf(-z3 * z3);
            hilo2(e0, e1, hv[dd * 2 + 0], lv[dd * 2 + 0]);
            hilo2(e2, e3, hv[dd * 2 + 1], lv[dd * 2 + 1]);
        }
        int kb = kh * 16 + jp * 8;
        *(uint4*)(aAh + (r * LSTR + kb) * 2) = make_uint4(hv[0], hv[1], hv[2], hv[3]);
        *(uint4*)(aAl + (r * LSTR + kb) * 2) = make_uint4(lv[0], lv[1], lv[2], lv[3]);
    }
}
__device__ __forceinline__ void store_silu(char* aAh, char* aAl, const float* pv, int r, int kh) {
    #pragma unroll
    for (int q = 0; q < 2; q++) {
        uint32_t hv[4], lv[4];
        #pragma unroll
        for (int p = 0; p < 4; p++) {
            float a = silu_f(pv[q * 8 + 2 * p]);
            float b = silu_f(pv[q * 8 + 2 * p + 1]);
            hilo2(a, b, hv[p], lv[p]);
        }
        int kb = kh * 16 + q * 8;
        *(uint4*)(aAh + (r * LSTR + kb) * 2) = make_uint4(hv[0], hv[1], hv[2], hv[3]);
        *(uint4*)(aAl + (r * LSTR + kb) * 2) = make_uint4(lv[0], lv[1], lv[2], lv[3]);
    }
}

// ------------------- layer GEMM (pipelined): h1 = dis*( [Basis|SiLU] @ W^T + bb ) ------
__global__ void __launch_bounds__(256) k_mma_layer(const float* __restrict__ bb,
                                                   const float* __restrict__ lng,
                                                   const float* __restrict__ lnb,
                                                   int set) {
    extern __shared__ char sm[];
    __shared__ float s_lg[128], s_lb[128];
    const int BUF = 40960;   // Ah 10240 | Al 10240 | Bh 10240 | Bl 10240
    int tid = threadIdx.x, lane = tid & 31, w = tid >> 5;
    int bm = blockIdx.x * 128;
    int r = tid & 127, kh = tid >> 7;
    int m0 = (w & 3) * 32, n0 = (w >> 2) * 64;
    int rb = set * 128;

    if (tid < 128) { s_lg[tid] = lng[tid]; s_lb[tid] = lnb[tid]; }
    float mu = g_mu[set][bm + r];
    float rs = g_rs[set][bm + r];

    float acc[2][8][4];
    #pragma unroll
    for (int a = 0; a < 2; a++)
        #pragma unroll
        for (int b = 0; b < 8; b++)
            #pragma unroll
            for (int c = 0; c < 4; c++) acc[a][b][c] = 0.f;

    uint32_t sb = smem_u32(sm);
    uint32_t offA = ((m0 + (lane & 15)) * LSTR + (lane >> 4) * 8) * 2;
    uint32_t offB = ((n0 + (lane & 7) + ((lane & 16) ? 8 : 0)) * LSTR + ((lane >> 3) & 1) * 8) * 2;

    float pv[16];
    uint4 pbh[2], pbl[2];
    {
        int d0 = rb + kh * 4;
        #pragma unroll
        for (int j = 0; j < 4; j++) pv[j] = g_XT[(size_t)(d0 + j) * NP + bm + r];
        const uint4* sh = (const uint4*)g_WBh;
        const uint4* sl = (const uint4*)g_WBl;
        pbh[0] = sh[tid]; pbh[1] = sh[tid + 256];
        pbl[0] = sl[tid]; pbl[1] = sl[tid + 256];
    }
    __syncthreads();   // s_lg/s_lb ready

    for (int c = 0; c < 20; c++) {
        int cur = c & 1;
        char* base = sm + cur * BUF;
        if (c < 16) store_basis(base, base + 10240, pv, r, kh, mu, rs,
                                &s_lg[c * 8 + kh * 4], &s_lb[c * 8 + kh * 4]);
        else        store_silu (base, base + 10240, pv, r, kh);
        {
            int n = tid >> 2, kq = tid & 3;
            int i2 = tid + 256;
            int n2 = i2 >> 2, kq2 = i2 & 3;
            *(uint4*)(base + 20480 + (n * LSTR + kq * 8) * 2)  = pbh[0];
            *(uint4*)(base + 20480 + (n2 * LSTR + kq2 * 8) * 2) = pbh[1];
            *(uint4*)(base + 30720 + (n * LSTR + kq * 8) * 2)  = pbl[0];
            *(uint4*)(base + 30720 + (n2 * LSTR + kq2 * 8) * 2) = pbl[1];
        }
        __syncthreads();
        if (c < 19) {
            int cn = c + 1;
            if (cn < 16) {
                int d0 = rb + cn * 8 + kh * 4;
                #pragma unroll
                for (int j = 0; j < 4; j++) pv[j] = g_XT[(size_t)(d0 + j) * NP + bm + r];
            } else {
                int sd0 = rb + (cn - 16) * 32 + kh * 16;
                #pragma unroll
                for (int q = 0; q < 16; q++) pv[q] = g_XT[(size_t)(sd0 + q) * NP + bm + r];
            }
            const uint4* sh = (const uint4*)g_WBh + cn * 512;
            const uint4* sl = (const uint4*)g_WBl + cn * 512;
            pbh[0] = sh[tid]; pbh[1] = sh[tid + 256];
            pbl[0] = sl[tid]; pbl[1] = sl[tid + 256];
        }
        uint32_t aAh = sb + cur * BUF, aAl = aAh + 10240;
        uint32_t aBh = aAh + 20480,   aBl = aAh + 30720;
        #pragma unroll
        for (int ks = 0; ks < 2; ks++) {
            uint32_t kadd = ks * 32;
            uint32_t ah[2][4], al[2][4];
            ldsm4(ah[0][0], ah[0][1], ah[0][2], ah[0][3], aAh + offA + kadd);
            ldsm4(ah[1][0], ah[1][1], ah[1][2], ah[1][3], aAh + offA + kadd + 16 * LSTR * 2);
            ldsm4(al[0][0], al[0][1], al[0][2], al[0][3], aAl + offA + kadd);
            ldsm4(al[1][0], al[1][1], al[1][2], al[1][3], aAl + offA + kadd + 16 * LSTR * 2);
            #pragma unroll
            for (int p = 0; p < 4; p++) {
                uint32_t bh[4], bl[4];
                uint32_t po = (uint32_t)(p * 16 * LSTR * 2);
                ldsm4(bh[0], bh[1], bh[2], bh[3], aBh + offB + kadd + po);
                ldsm4(bl[0], bl[1], bl[2], bl[3], aBl + offB + kadd + po);
                #pragma unroll
                for (int mf = 0; mf < 2; mf++) {
                    mmabf(acc[mf][2 * p],     ah[mf], bh[0], bh[1]);
                    mmabf(acc[mf][2 * p],     ah[mf], bl[0], bl[1]);
                    mmabf(acc[mf][2 * p],     al[mf], bh[0], bh[1]);
                    mmabf(acc[mf][2 * p + 1], ah[mf], bh[2], bh[3]);
                    mmabf(acc[mf][2 * p + 1], ah[mf], bl[2], bl[3]);
                    mmabf(acc[mf][2 * p + 1], al[mf], bh[2], bh[3]);
                }
            }
        }
    }
    int gid = lane >> 2, tig = lane & 3;
    #pragma unroll
    for (int mf = 0; mf < 2; mf++) {
        int row = bm + m0 + mf * 16 + gid;
        float d0 = (row < NN) ? g_dis[row] : 0.f;
        float d1 = (row + 8 < NN) ? g_dis[row + 8] : 0.f;
        #pragma unroll
        for (int nf = 0; nf < 8; nf++) {
            int col = n0 + nf * 8 + tig * 2;
            if (row < NN) {
                float2 v = make_float2((acc[mf][nf][0] + bb[col]) * d0,
                                       (acc[mf][nf][1] + bb[col + 1]) * d0);
                *(float2*)&g_h1[(size_t)row * HH + col] = v;
            }
            if (row + 8 < NN) {
                float2 v = make_float2((acc[mf][nf][2] + bb[col]) * d1,
                                       (acc[mf][nf][3] + bb[col + 1]) * d1);
                *(float2*)&g_h1[(size_t)(row + 8) * HH + col] = v;
            }
        }
    }
}

// ------------------- output GEMM (pipelined, N=40) -------------------
__global__ void __launch_bounds__(256) k_mma_out(const float* __restrict__ bbo,
                                                 const float* __restrict__ lng,
                                                 const float* __restrict__ lnb,
                                                 float* __restrict__ out) {
    extern __shared__ char sm[];
    __shared__ float s_lg[512], s_lb[512];
    const int BUF = 26880;   // Ah 10240 | Al 10240 | Bh 3200 | Bl 3200
    int tid = threadIdx.x, lane = tid & 31, w = tid >> 5;
    int bm = blockIdx.x * 128;
    int r = tid & 127, kh = tid >> 7;
    int m0 = w * 16;

    #pragma unroll
    for (int i = tid; i < 512; i += 256) { s_lg[i] = lng[i]; s_lb[i] = lnb[i]; }
    float mu, rs;
    {
        float s = g_osum[bm + r], sq = g_osq[bm + r];
        mu = s * (1.0f / 512.0f);
        float var = sq * (1.0f / 512.0f) - mu * mu;
        rs = rsqrtf(var + 1e-5f);
    }

    float acc[5][4];
    #pragma unroll
    for (int b = 0; b < 5; b++)
        #pragma unroll
        for (int c = 0; c < 4; c++) acc[b][c] = 0.f;

    uint32_t sb = smem_u32(sm);
    uint32_t offA  = ((m0 + (lane & 15)) * LSTR + (lane >> 4) * 8) * 2;
    uint32_t offB  = (((lane & 7) + ((lane & 16) ? 8 : 0)) * LSTR + ((lane >> 3) & 1) * 8) * 2;
    uint32_t offB2 = ((32 + (lane & 7)) * LSTR + ((lane >> 3) & 1) * 8) * 2;

    float pv[16];
    uint4 pbh, pbl;
    {
        int d0 = kh * 4;
        #pragma unroll
        for (int j = 0; j < 4; j++) pv[j] = g_XT[(size_t)(d0 + j) * NP + bm + r];
        if (tid < 160) {
            pbh = ((const uint4*)g_WOh)[tid];
            pbl = ((const uint4*)g_WOl)[tid];
        }
    }
    __syncthreads();   // s_lg/s_lb ready

    for (int c = 0; c < 80; c++) {
        int cur = c & 1;
        char* base = sm + cur * BUF;
        if (c < 64) store_basis(base, base + 10240, pv, r, kh, mu, rs,
                                &s_lg[c * 8 + kh * 4], &s_lb[c * 8 + kh * 4]);
        else        store_silu (base, base + 10240, pv, r, kh);
        if (tid < 160) {
            int n = tid >> 2, kq = tid & 3;
            *(uint4*)(base + 20480 + (n * LSTR + kq * 8) * 2) = pbh;
            *(uint4*)(base + 23680 + (n * LSTR + kq * 8) * 2) = pbl;
        }
        __syncthreads();
        if (c < 79) {
            int cn = c + 1;
            if (cn < 64) {
                int d0 = cn * 8 + kh * 4;
                #pragma unroll
                for (int j = 0; j < 4; j++) pv[j] = g_XT[(size_t)(d0 + j) * NP + bm + r];
            } else {
                int sd0 = (cn - 64) * 32 + kh * 16;
                #pragma unroll
                for (int q = 0; q < 16; q++) pv[q] = g_XT[(size_t)(sd0 + q) * NP + bm + r];
            }
            if (tid < 160) {
                pbh = ((const uint4*)g_WOh + cn * 160)[tid];
                pbl = ((const uint4*)g_WOl + cn * 160)[tid];
            }
        }
        uint32_t aAh = sb + cur * BUF, aAl = aAh + 10240;
        uint32_t aBh = aAh + 20480,   aBl = aAh + 23680;
        #pragma unroll
        for (int ks = 0; ks < 2; ks++) {
            uint32_t kadd = ks * 32;
            uint32_t ah[4], al[4];
            ldsm4(ah[0], ah[1], ah[2], ah[3], aAh + offA + kadd);
            ldsm4(al[0], al[1], al[2], al[3], aAl + offA + kadd);
            #pragma unroll
            for (int g = 0; g < 2; g++) {
                uint32_t bh[4], bl[4];
                uint32_t po = (uint32_t)(g * 16 * LSTR * 2);
                ldsm4(bh[0], bh[1], bh[2], bh[3], aBh + offB + kadd + po);
                ldsm4(bl[0], bl[1], bl[2], bl[3], aBl + offB + kadd + po);
                mmabf(acc[2 * g],     ah, bh[0], bh[1]);
                mmabf(acc[2 * g],     ah, bl[0], bl[1]);
                mmabf(acc[2 * g],     al, bh[0], bh[1]);
                mmabf(acc[2 * g + 1], ah, bh[2], bh[3]);
                mmabf(acc[2 * g + 1], ah, bl[2], bl[3]);
                mmabf(acc[2 * g + 1], al, bh[2], bh[3]);
            }
            {
                uint32_t b0, b1, c0, c1;
                ldsm2(b0, b1, aBh + offB2 + kadd);
                ldsm2(c0, c1, aBl + offB2 + kadd);
                mmabf(acc[4], ah, b0, b1);
                mmabf(acc[4], ah, c0, c1);
                mmabf(acc[4], al, b0, b1);
            }
        }
    }
    int gid = lane >> 2, tig = lane & 3;
    int row = bm + m0 + gid;
    #pragma unroll
    for (int nf = 0; nf < 5; nf++) {
        int col = nf * 8 + tig * 2;
        if (row < NN) {
            float2 v = make_float2(acc[nf][0] + bbo[col], acc[nf][1] + bbo[col + 1]);
            *(float2*)&out[(size_t)row * CC + col] = v;
        }
        if (row + 8 < NN) {
            float2 v = make_float2(acc[nf][2] + bbo[col], acc[nf][3] + bbo[col + 1]);
            *(float2*)&out[(size_t)(row + 8) * CC + col] = v;
        }
    }
}

// ------------------- GCN aggregation (pull via CSR; h1 pre-scaled by dis) -------------------
__global__ void __launch_bounds__(256) k_gcn() {
    int warp = blockIdx.x * 8 + (threadIdx.x >> 5);
    if (warp >= NN) return;
    int l = threadIdx.x & 31;
    float dn = g_dis[warp];
    float4 acc = *(const float4*)(g_h1 + (size_t)warp * HH + l * 4);
    int lo = g_off[warp], hi = g_off[warp + 1];
    for (int e = lo; e < hi; e++) {
        int sidx = g_csr[e];
        float4 hv = *(const float4*)(g_h1 + (size_t)sidx * HH + l * 4);
        acc.x += hv.x; acc.y += hv.y; acc.z += hv.z; acc.w += hv.w;
    }
    float4 rr = make_float4(dn * acc.x, dn * acc.y, dn * acc.z, dn * acc.w);
    *(float4*)(g_h2 + (size_t)warp * HH + l * 4) = rr;
}

// ------------------- BatchNorm stats -------------------
__global__ void k_zero_stats() {
    int t = threadIdx.x;
    g_sum[t] = 0.0; g_sumsq[t] = 0.0;
}
__global__ void __launch_bounds__(128) k_bn_partial() {
    int t = threadIdx.x;
    int r0 = blockIdx.x * 64;
    float s = 0.f, s2 = 0.f;
    #pragma unroll 4
    for (int r = 0; r < 64; r++) {
        int row = r0 + r;
        if (row < NN) {
            float v = g_h2[(size_t)row * HH + t];
            s += v; s2 += v * v;
        }
    }
    atomicAdd(&g_sum[t], (double)s);
    atomicAdd(&g_sumsq[t], (double)s2);
}
__global__ void k_bn_finalize(const float* __restrict__ bng, const float* __restrict__ bnb) {
    int t = threadIdx.x;
    double m = g_sum[t] / (double)NN;
    double var = g_sumsq[t] / (double)NN - m * m;
    float sc = bng[t] * rsqrtf((float)var + 1e-5f);
    g_bns[t] = sc;
    g_bnb[t] = bnb[t] - (float)m * sc;
}

// ------------------- launch -------------------
extern "C" void kernel_launch(void* const* d_in, const int* in_sizes, int n_in,
                              void* d_out, int out_size) {
    const float* x      = (const float*)d_in[0];
    const void*  eidx   = d_in[1];
    const float* ln_g   = (const float*)d_in[2];
    const float* ln_b   = (const float*)d_in[3];
    const float* sw     = (const float*)d_in[4];
    const float* bw     = (const float*)d_in[5];
    const float* bb     = (const float*)d_in[6];
    // d_in[7] = gcn_bias: cancelled exactly by the following BatchNorm -> skipped
    const float* bn_g   = (const float*)d_in[8];
    const float* bn_b   = (const float*)d_in[9];
    const float* ln_go  = (const float*)d_in[10];
    const float* ln_bo  = (const float*)d_in[11];
    const float* sw_o   = (const float*)d_in[12];
    const float* bw_o   = (const float*)d_in[13];
    const float* bb_o   = (const float*)d_in[14];
    float* out = (float*)d_out;

    const int SMEM_L = 2 * 40960;   // 81920
    const int SMEM_O = 2 * 26880;   // 53760
    cudaFuncSetAttribute(k_mma_layer, cudaFuncAttributeMaxDynamicSharedMemorySize, SMEM_L);
    cudaFuncSetAttribute(k_mma_out,   cudaFuncAttributeMaxDynamicSharedMemorySize, SMEM_O);

    // graph / CSR build
    k_detect<<<1, 1>>>((const unsigned*)eidx);
    k_zero_cnt<<<(NN + 255) / 256, 256>>>();
    k_decode<<<(EE + 255) / 256, 256>>>(eidx);
    k_dis<<<(NN + 255) / 256, 256>>>();
    k_scan<<<1, 1024>>>();
    k_fill<<<(EE + 255) / 256, 256>>>();

    // feature path init + weight prep (layer 0 ONLY — g_WBh/l holds one layer at a time)
    k_tx<<<(NN + 31) / 32, 256>>>(x);
    k_prepWB<<<(640 * 128 + 255) / 256, 256>>>(sw, bw, 0);
    k_prepWO<<<(2560 * 40 + 255) / 256, 256>>>(sw_o, bw_o);

    const int GT = (NN + 127) / 128;  // 391 M-tiles

    for (int i = 0; i < LL; i++) {
        if (i > 0) k_prepWB<<<(640 * 128 + 255) / 256, 256>>>(sw, bw, i);
        k_mma_layer<<<GT, 256, SMEM_L>>>(bb + i * HH, ln_g + i * DD, ln_b + i * DD, i);
        k_gcn<<<(NN + 7) / 8, 256>>>();
        k_zero_stats<<<1, 128>>>();
        k_bn_partial<<<(NN + 63) / 64, 128>>>();
        k_bn_finalize<<<1, 128>>>(bn_g + i * HH, bn_b + i * HH);
        k_bnt<<<(NN + 31) / 32, 256>>>((i + 1) * 128, i + 1);
    }

    k_mma_out<<<GT, 256, SMEM_O>>>(bb_o, ln_go, ln_bo, out);
}